// round 1
// baseline (speedup 1.0000x reference)
#include <cuda_runtime.h>
#include <math.h>

// Problem constants (fixed shapes from reference)
#define BB   4
#define LL   2048
#define DD   256
#define DIN  512          // d_inner
#define NSS  16           // d_state
#define DTR_ 16           // dt_rank
#define DFF_ 1024
#define TOK  (BB*LL)      // 8192 tokens

// ---------------- scratch (static device memory; no allocs) ----------------
__device__ float g_xz   [TOK * 2 * DIN];   // in_proj output [tok,1024]
__device__ float g_xconv[TOK * DIN];       // silu(conv(xi))
__device__ float g_wt   [DIN * 48];        // x_proj_w transposed [512,48]
__device__ float g_xdbl [TOK * 48];        // dt(16)|B(16)|C(16)
__device__ float g_dt   [TOK * DIN];       // softplus(dt_proj)
__device__ float g_yg   [TOK * DIN];       // gated scan output
__device__ float g_ssm  [TOK * DD];        // out_proj output
__device__ float g_y1   [TOK * DD];        // LN1 output
__device__ float g_h1   [TOK * DFF_];      // gelu(fc1)
__device__ float g_f2   [TOK * DD];        // gelu(fc2)

// ---------------- math helpers ----------------
__device__ __forceinline__ float siluf(float v)     { return v / (1.f + __expf(-v)); }
__device__ __forceinline__ float geluf(float v)     { return 0.5f * v * (1.f + erff(v * 0.70710678118654752f)); }
__device__ __forceinline__ float softplusf(float v) { return fmaxf(v, 0.f) + log1pf(__expf(-fabsf(v))); }

// ---------------- generic SGEMM: C[M,N] = A[M,K(lda)] @ W[N,K]^T + bias, epilogue ----
// Assumes M%128==0, N%128==0, K%16==0 (true for all call sites).
// EPI: 0 = none, 1 = gelu, 2 = softplus
template<int EPI>
__global__ __launch_bounds__(256)
void gemm_kernel(const float* __restrict__ A, int lda,
                 const float* __restrict__ W,
                 const float* __restrict__ bias,
                 float* __restrict__ C, int M, int N, int K)
{
    __shared__ float As[16][132];   // k-major, padded
    __shared__ float Bs[16][132];

    const int tid = threadIdx.x;
    const int tx = tid & 15;        // N direction (8 cols each)
    const int ty = tid >> 4;        // M direction (8 rows each)
    const int rowBase = blockIdx.y * 128;
    const int colBase = blockIdx.x * 128;
    const int r  = tid >> 2;        // 0..63
    const int c4 = tid & 3;         // float4 slot along K

    float acc[8][8];
    #pragma unroll
    for (int i = 0; i < 8; i++)
        #pragma unroll
        for (int j = 0; j < 8; j++) acc[i][j] = 0.f;

    for (int kt = 0; kt < K; kt += 16) {
        #pragma unroll
        for (int rr = r; rr < 128; rr += 64) {
            float4 va = *reinterpret_cast<const float4*>(&A[(size_t)(rowBase + rr) * lda + kt + c4 * 4]);
            As[c4*4+0][rr] = va.x; As[c4*4+1][rr] = va.y;
            As[c4*4+2][rr] = va.z; As[c4*4+3][rr] = va.w;
            float4 vb = *reinterpret_cast<const float4*>(&W[(size_t)(colBase + rr) * K + kt + c4 * 4]);
            Bs[c4*4+0][rr] = vb.x; Bs[c4*4+1][rr] = vb.y;
            Bs[c4*4+2][rr] = vb.z; Bs[c4*4+3][rr] = vb.w;
        }
        __syncthreads();
        #pragma unroll
        for (int k = 0; k < 16; k++) {
            float a8[8], b8[8];
            #pragma unroll
            for (int i = 0; i < 8; i++) a8[i] = As[k][ty * 8 + i];
            #pragma unroll
            for (int j = 0; j < 8; j++) b8[j] = Bs[k][tx * 8 + j];
            #pragma unroll
            for (int i = 0; i < 8; i++)
                #pragma unroll
                for (int j = 0; j < 8; j++)
                    acc[i][j] = fmaf(a8[i], b8[j], acc[i][j]);
        }
        __syncthreads();
    }

    #pragma unroll
    for (int i = 0; i < 8; i++) {
        const int row = rowBase + ty * 8 + i;
        #pragma unroll
        for (int j = 0; j < 8; j++) {
            const int col = colBase + tx * 8 + j;
            float v = acc[i][j] + bias[col];
            if (EPI == 1)      v = geluf(v);
            else if (EPI == 2) v = softplusf(v);
            C[(size_t)row * N + col] = v;
        }
    }
}

// ---------------- causal depthwise conv (taps=4) + silu ----------------
__global__ __launch_bounds__(256)
void conv_silu_kernel(const float* __restrict__ xz,
                      const float* __restrict__ cw,
                      const float* __restrict__ cb,
                      float* __restrict__ xc)
{
    const int idx = blockIdx.x * blockDim.x + threadIdx.x;  // TOK*DIN
    const int d = idx & (DIN - 1);
    const int t = idx >> 9;
    const int l = t & (LL - 1);
    const float w0 = cw[d*4+0], w1 = cw[d*4+1], w2 = cw[d*4+2], w3 = cw[d*4+3];
    const float* p = xz + (size_t)t * (2 * DIN) + d;   // xi channel d at token t
    float acc = cb[d] + w3 * p[0];
    if (l >= 1) acc = fmaf(w2, p[-(2*DIN)],   acc);
    if (l >= 2) acc = fmaf(w1, p[-2*(2*DIN)], acc);
    if (l >= 3) acc = fmaf(w0, p[-3*(2*DIN)], acc);
    xc[idx] = siluf(acc);
}

// ---------------- transpose x_proj_w [48,512] -> [512,48] ----------------
__global__ void transpose_w_kernel(const float* __restrict__ W, float* __restrict__ Wt)
{
    const int idx = blockIdx.x * blockDim.x + threadIdx.x;
    if (idx < 48 * DIN) {
        const int j = idx / DIN, k = idx % DIN;
        Wt[k * 48 + j] = W[idx];
    }
}

// ---------------- x_proj: out[tok,48] = xc[tok,512] @ Wt ----------------
__global__ __launch_bounds__(128)
void xproj_kernel(const float* __restrict__ xc, const float* __restrict__ Wt,
                  float* __restrict__ out)
{
    const int token = blockIdx.x * blockDim.x + threadIdx.x;
    float acc[48];
    #pragma unroll
    for (int j = 0; j < 48; j++) acc[j] = 0.f;
    const float* xr = xc + (size_t)token * DIN;
    for (int k = 0; k < DIN; k += 4) {
        const float4 xv = *reinterpret_cast<const float4*>(xr + k);
        const float xs[4] = {xv.x, xv.y, xv.z, xv.w};
        #pragma unroll
        for (int kk = 0; kk < 4; kk++) {
            const float4* wr = reinterpret_cast<const float4*>(Wt + (size_t)(k + kk) * 48);
            #pragma unroll
            for (int j4 = 0; j4 < 12; j4++) {
                const float4 w = wr[j4];   // broadcast across warp -> L1 hit
                acc[j4*4+0] = fmaf(xs[kk], w.x, acc[j4*4+0]);
                acc[j4*4+1] = fmaf(xs[kk], w.y, acc[j4*4+1]);
                acc[j4*4+2] = fmaf(xs[kk], w.z, acc[j4*4+2]);
                acc[j4*4+3] = fmaf(xs[kk], w.w, acc[j4*4+3]);
            }
        }
    }
    float* o = out + (size_t)token * 48;
    #pragma unroll
    for (int j = 0; j < 48; j++) o[j] = acc[j];
}

// ---------------- selective scan + D skip + silu(z) gate ----------------
// One lane per (b, d, n) state; 16 lanes reduce y = sum_n h*C via shfl.
// Two channels per warp (lanes 0-15 / 16-31).
__global__ __launch_bounds__(256)
void scan_kernel(const float* __restrict__ dt, const float* __restrict__ xdbl,
                 const float* __restrict__ xc, const float* __restrict__ xz,
                 const float* __restrict__ A_log, const float* __restrict__ D_ssm,
                 float* __restrict__ yg)
{
    const int lane   = threadIdx.x & 31;
    const int n      = lane & 15;
    const int warp_g = (blockIdx.x * blockDim.x + threadIdx.x) >> 5;
    const int ch     = warp_g * 2 + (lane >> 4);     // 0..2047
    const int b = ch >> 9, d = ch & (DIN - 1);

    const float Aval = -expf(A_log[d * NSS + n]);
    const float Dv   = D_ssm[d];
    float h = 0.f;

    size_t t = (size_t)b * LL;
    for (int l = 0; l < LL; l++, t++) {
        const float dtv = dt[t * DIN + d];                 // broadcast in half-warp
        const float xv  = xc[t * DIN + d];                 // broadcast
        const float Bv  = xdbl[t * 48 + DTR_ + n];
        const float Cv  = xdbl[t * 48 + DTR_ + NSS + n];
        const float dA  = __expf(dtv * Aval);
        h = fmaf(dA, h, dtv * Bv * xv);
        float p = h * Cv;
        p += __shfl_xor_sync(0xffffffffu, p, 8);
        p += __shfl_xor_sync(0xffffffffu, p, 4);
        p += __shfl_xor_sync(0xffffffffu, p, 2);
        p += __shfl_xor_sync(0xffffffffu, p, 1);
        if (n == 0) {
            const float y  = p + xv * Dv;
            const float zv = xz[t * (2 * DIN) + DIN + d];
            yg[t * DIN + d] = y * siluf(zv);
        }
    }
}

// ---------------- fused residual-add + LayerNorm (D=256, 1 row / block) ----
__global__ __launch_bounds__(256)
void ln_add_kernel(const float* __restrict__ a, const float* __restrict__ badd,
                   const float* __restrict__ g, const float* __restrict__ beta,
                   float* __restrict__ out)
{
    const int row = blockIdx.x;
    const int tid = threadIdx.x;
    const float v = a[(size_t)row * DD + tid] + badd[(size_t)row * DD + tid];

    float s = v, s2 = v * v;
    #pragma unroll
    for (int m = 16; m > 0; m >>= 1) {
        s  += __shfl_xor_sync(0xffffffffu, s,  m);
        s2 += __shfl_xor_sync(0xffffffffu, s2, m);
    }
    __shared__ float sh[8], sh2[8];
    if ((tid & 31) == 0) { sh[tid >> 5] = s; sh2[tid >> 5] = s2; }
    __syncthreads();
    float ts = 0.f, ts2 = 0.f;
    #pragma unroll
    for (int i = 0; i < 8; i++) { ts += sh[i]; ts2 += sh2[i]; }
    const float mean = ts * (1.f / DD);
    const float var  = ts2 * (1.f / DD) - mean * mean;
    const float inv  = rsqrtf(var + 1e-5f);
    out[(size_t)row * DD + tid] = (v - mean) * inv * g[tid] + beta[tid];
}

// ---------------- launch ----------------
extern "C" void kernel_launch(void* const* d_in, const int* in_sizes, int n_in,
                              void* d_out, int out_size)
{
    const float* x          = (const float*)d_in[0];
    const float* in_proj_w  = (const float*)d_in[1];
    const float* in_proj_b  = (const float*)d_in[2];
    const float* conv_w     = (const float*)d_in[3];
    const float* conv_b     = (const float*)d_in[4];
    const float* x_proj_w   = (const float*)d_in[5];
    const float* dt_proj_w  = (const float*)d_in[6];
    const float* dt_proj_b  = (const float*)d_in[7];
    const float* A_log      = (const float*)d_in[8];
    const float* D_ssm      = (const float*)d_in[9];
    const float* out_proj_w = (const float*)d_in[10];
    const float* out_proj_b = (const float*)d_in[11];
    const float* ln1_g      = (const float*)d_in[12];
    const float* ln1_b      = (const float*)d_in[13];
    const float* fc1_w      = (const float*)d_in[14];
    const float* fc1_b      = (const float*)d_in[15];
    const float* fc2_w      = (const float*)d_in[16];
    const float* fc2_b      = (const float*)d_in[17];
    const float* ln2_g      = (const float*)d_in[18];
    const float* ln2_b      = (const float*)d_in[19];
    float* out = (float*)d_out;

    float *xz, *xconv, *wt, *xdbl, *dtb, *ygb, *ssm, *y1, *h1, *f2;
    cudaGetSymbolAddress((void**)&xz,    g_xz);
    cudaGetSymbolAddress((void**)&xconv, g_xconv);
    cudaGetSymbolAddress((void**)&wt,    g_wt);
    cudaGetSymbolAddress((void**)&xdbl,  g_xdbl);
    cudaGetSymbolAddress((void**)&dtb,   g_dt);
    cudaGetSymbolAddress((void**)&ygb,   g_yg);
    cudaGetSymbolAddress((void**)&ssm,   g_ssm);
    cudaGetSymbolAddress((void**)&y1,    g_y1);
    cudaGetSymbolAddress((void**)&h1,    g_h1);
    cudaGetSymbolAddress((void**)&f2,    g_f2);

    // 1) in_proj: [8192,256] @ [1024,256]^T -> [8192,1024]
    gemm_kernel<0><<<dim3(2 * DIN / 128, TOK / 128), 256>>>(x, DD, in_proj_w, in_proj_b, xz, TOK, 2 * DIN, DD);
    // 2) causal conv + silu
    conv_silu_kernel<<<(TOK * DIN) / 256, 256>>>(xz, conv_w, conv_b, xconv);
    // 3) x_proj (N=48): transpose weights then per-token dot
    transpose_w_kernel<<<(48 * DIN + 255) / 256, 256>>>(x_proj_w, wt);
    xproj_kernel<<<TOK / 128, 128>>>(xconv, wt, xdbl);
    // 4) dt_proj + softplus: [8192,16(lda48)] @ [512,16]^T
    gemm_kernel<2><<<dim3(DIN / 128, TOK / 128), 256>>>(xdbl, 48, dt_proj_w, dt_proj_b, dtb, TOK, DIN, DTR_);
    // 5) selective scan + gate
    scan_kernel<<<(BB * DIN) / 16, 256>>>(dtb, xdbl, xconv, xz, A_log, D_ssm, ygb);
    // 6) out_proj: [8192,512] @ [256,512]^T
    gemm_kernel<0><<<dim3(DD / 128, TOK / 128), 256>>>(ygb, DIN, out_proj_w, out_proj_b, ssm, TOK, DD, DIN);
    // 7) LN1(x + ssm)
    ln_add_kernel<<<TOK, 256>>>(x, ssm, ln1_g, ln1_b, y1);
    // 8) fc1 + gelu
    gemm_kernel<1><<<dim3(DFF_ / 128, TOK / 128), 256>>>(y1, DD, fc1_w, fc1_b, h1, TOK, DFF_, DD);
    // 9) fc2 + gelu
    gemm_kernel<1><<<dim3(DD / 128, TOK / 128), 256>>>(h1, DFF_, fc2_w, fc2_b, f2, TOK, DD, DFF_);
    // 10) LN2(y1 + ffn) -> output
    ln_add_kernel<<<TOK, 256>>>(y1, f2, ln2_g, ln2_b, out);
}

// round 4
// speedup vs baseline: 1.3155x; 1.3155x over previous
#include <cuda_runtime.h>
#include <cuda_bf16.h>
#include <math.h>
#include <stdint.h>

// Problem constants (fixed shapes)
#define BB   4
#define LL   2048
#define DD   256
#define DIN  512
#define NSS  16
#define DTR_ 16
#define DFF_ 1024
#define TOK  (BB*LL)      // 8192

// ---------------- scratch (static device memory) ----------------
__device__ float          g_xz    [TOK * 2 * DIN];
__device__ float          g_xconv [TOK * DIN];
__device__ __nv_bfloat16  g_xconvb[TOK * DIN];
__device__ float          g_xdbl  [TOK * 64];        // dt(16)|B(16)|C(16)|pad(16)
__device__ float          g_dt    [TOK * DIN];
__device__ __nv_bfloat16  g_ygb   [TOK * DIN];
__device__ float          g_ssm   [TOK * DD];
__device__ float          g_y1    [TOK * DD];
__device__ __nv_bfloat16  g_y1b   [TOK * DD];
__device__ __nv_bfloat16  g_h1b   [TOK * DFF_];
__device__ float          g_f2    [TOK * DD];
__device__ __nv_bfloat16  g_xb    [TOK * DD];
__device__ __nv_bfloat16  g_w_in  [2 * DIN * DD];
__device__ __nv_bfloat16  g_w_xp  [64 * DIN];
__device__ __nv_bfloat16  g_w_out [DD * DIN];
__device__ __nv_bfloat16  g_w_fc1 [DFF_ * DD];
__device__ __nv_bfloat16  g_w_fc2 [DD * DFF_];
__device__ float          g_zero  [64];

// ---------------- math helpers ----------------
__device__ __forceinline__ float siluf(float v)     { return v / (1.f + __expf(-v)); }
__device__ __forceinline__ float geluf(float v)     { return 0.5f * v * (1.f + erff(v * 0.70710678118654752f)); }
__device__ __forceinline__ float softplusf(float v) { return fmaxf(v, 0.f) + log1pf(__expf(-fabsf(v))); }

__device__ __forceinline__ uint32_t smem_u32(const void* p) {
    uint32_t a;
    asm("{ .reg .u64 t; cvta.to.shared.u64 t, %1; cvt.u32.u64 %0, t; }" : "=r"(a) : "l"(p));
    return a;
}
__device__ __forceinline__ void ldsm4(uint32_t& r0, uint32_t& r1, uint32_t& r2, uint32_t& r3, uint32_t addr) {
    asm volatile("ldmatrix.sync.aligned.m8n8.x4.shared.b16 {%0,%1,%2,%3}, [%4];"
                 : "=r"(r0), "=r"(r1), "=r"(r2), "=r"(r3) : "r"(addr));
}
__device__ __forceinline__ void mma16816(float* c, const uint32_t* a, const uint32_t* b) {
    asm volatile("mma.sync.aligned.m16n8k16.row.col.f32.bf16.bf16.f32 "
                 "{%0,%1,%2,%3},{%4,%5,%6,%7},{%8,%9},{%0,%1,%2,%3};"
                 : "+f"(c[0]), "+f"(c[1]), "+f"(c[2]), "+f"(c[3])
                 : "r"(a[0]), "r"(a[1]), "r"(a[2]), "r"(a[3]), "r"(b[0]), "r"(b[1]));
}
__device__ __forceinline__ void cp16(uint32_t dst, const void* src) {
    asm volatile("cp.async.cg.shared.global [%0], [%1], 16;" :: "r"(dst), "l"(src));
}
#define CP_COMMIT() asm volatile("cp.async.commit_group;" ::: "memory")

// =======================================================================
// SM80-style pipelined bf16 GEMM: C[M,N] = act(A[M,K] @ W[N,K]^T + bias)
// BM=128, BN template (128/64), BK=32, 256 threads = 2(M) x 4(N) warps.
// Warp tile: 64 x (BN/4). mma m16n8k16, fp32 accum.
// EPI: 0 none, 1 gelu.  OUTT: 0 fp32, 1 bf16.
// =======================================================================
template<int BN, int EPI, int OUTT>
__global__ __launch_bounds__(256)
void mma_gemm(const __nv_bfloat16* __restrict__ A, const __nv_bfloat16* __restrict__ W,
              const float* __restrict__ bias, void* __restrict__ C, int N, int K)
{
    constexpr int BM  = 128;
    constexpr int BK  = 32;
    constexpr int AST = 40;                 // padded row stride in elems (80B, odd multiple of 16B)
    constexpr int NT  = BN / 32;            // n8-tiles per warp (4 or 2)

    __shared__ __align__(16) __nv_bfloat16 sA[2][BM * AST];
    __shared__ __align__(16) __nv_bfloat16 sB[2][BN * AST];

    const int tid  = threadIdx.x;
    const int wid  = tid >> 5;
    const int lane = tid & 31;
    const int warp_m = wid & 1;             // 0..1
    const int warp_n = wid >> 1;            // 0..3
    const int rowBase = blockIdx.y * BM;
    const int colBase = blockIdx.x * BN;
    const int NK = K >> 5;                  // BK=32 chunks

    // async copy of one stage
    auto prefetch = [&](int s, int kc) {
        #pragma unroll
        for (int i = 0; i < 2; i++) {       // 512 A chunks of 16B
            const int cidx = i * 256 + tid;
            const int row = cidx >> 2, c4 = cidx & 3;
            cp16(smem_u32(&sA[s][row * AST + c4 * 8]),
                 A + (size_t)(rowBase + row) * K + kc * BK + c4 * 8);
        }
        #pragma unroll
        for (int i = 0; i < BN / 64; i++) { // BN*4 B chunks
            const int cidx = i * 256 + tid;
            const int row = cidx >> 2, c4 = cidx & 3;
            cp16(smem_u32(&sB[s][row * AST + c4 * 8]),
                 W + (size_t)(colBase + row) * K + kc * BK + c4 * 8);
        }
    };

    float acc[4][NT][4];
    #pragma unroll
    for (int mi = 0; mi < 4; mi++)
        #pragma unroll
        for (int ni = 0; ni < NT; ni++)
            #pragma unroll
            for (int r = 0; r < 4; r++) acc[mi][ni][r] = 0.f;

    prefetch(0, 0);
    CP_COMMIT();

    for (int kt = 0; kt < NK; kt++) {
        if (kt + 1 < NK) {
            prefetch((kt + 1) & 1, kt + 1);
            CP_COMMIT();
            asm volatile("cp.async.wait_group 1;" ::: "memory");
        } else {
            asm volatile("cp.async.wait_group 0;" ::: "memory");
        }
        __syncthreads();

        const int s = kt & 1;
        #pragma unroll
        for (int k = 0; k < 2; k++) {       // two k16 steps per BK=32
            // A fragments: 4 m16 tiles
            uint32_t af[4][4];
            #pragma unroll
            for (int mi = 0; mi < 4; mi++) {
                const int row = warp_m * 64 + mi * 16 + (lane & 15);
                const int col = k * 16 + (lane >> 4) * 8;
                ldsm4(af[mi][0], af[mi][1], af[mi][2], af[mi][3],
                      smem_u32(&sA[s][row * AST + col]));
            }
            // B fragments: NT n8 tiles, loaded in pairs via x4
            uint32_t bf[NT][2];
            #pragma unroll
            for (int np = 0; np < NT / 2; np++) {
                const int n0 = warp_n * (NT * 8) + np * 16;
                const int q  = lane >> 3;
                const int row = n0 + (q & 1) * 8 + (lane & 7);
                const int col = k * 16 + (q >> 1) * 8;
                uint32_t r0, r1, r2, r3;
                ldsm4(r0, r1, r2, r3, smem_u32(&sB[s][row * AST + col]));
                bf[np*2][0] = r0; bf[np*2+1][0] = r1;
                bf[np*2][1] = r2; bf[np*2+1][1] = r3;
            }
            #pragma unroll
            for (int mi = 0; mi < 4; mi++)
                #pragma unroll
                for (int ni = 0; ni < NT; ni++)
                    mma16816(acc[mi][ni], af[mi], bf[ni]);
        }
        __syncthreads();
    }

    // epilogue: direct stores (2 consecutive elems per thread per fragment row)
    const int g  = lane >> 2;
    const int c2 = (lane & 3) * 2;
    #pragma unroll
    for (int mi = 0; mi < 4; mi++) {
        const int row0 = rowBase + warp_m * 64 + mi * 16 + g;
        #pragma unroll
        for (int ni = 0; ni < NT; ni++) {
            const int col = colBase + warp_n * (NT * 8) + ni * 8 + c2;
            const float b0 = bias[col], b1 = bias[col + 1];
            float v00 = acc[mi][ni][0] + b0, v01 = acc[mi][ni][1] + b1;
            float v10 = acc[mi][ni][2] + b0, v11 = acc[mi][ni][3] + b1;
            if (EPI == 1) { v00 = geluf(v00); v01 = geluf(v01); v10 = geluf(v10); v11 = geluf(v11); }
            if (OUTT == 0) {
                *(float2*)((float*)C + (size_t)row0 * N + col)       = make_float2(v00, v01);
                *(float2*)((float*)C + (size_t)(row0 + 8) * N + col) = make_float2(v10, v11);
            } else {
                __nv_bfloat16* Cb = (__nv_bfloat16*)C;
                *(__nv_bfloat162*)(Cb + (size_t)row0 * N + col)       = __float22bfloat162_rn(make_float2(v00, v01));
                *(__nv_bfloat162*)(Cb + (size_t)(row0 + 8) * N + col) = __float22bfloat162_rn(make_float2(v10, v11));
            }
        }
    }
}

// ---------------- fp32 -> bf16 converters ----------------
__global__ void cvt_bf16_kernel(const float* __restrict__ in, __nv_bfloat16* __restrict__ out, int n)
{
    int i = blockIdx.x * blockDim.x + threadIdx.x;
    if (i < n) out[i] = __float2bfloat16(in[i]);
}
__global__ void pad_xprojw_kernel(const float* __restrict__ W, __nv_bfloat16* __restrict__ out)
{
    int i = blockIdx.x * blockDim.x + threadIdx.x;      // 64*512
    int r = i >> 9, k = i & 511;
    out[i] = __float2bfloat16(r < 48 ? W[r * 512 + k] : 0.f);
}

// ---------------- SIMT SGEMM (dt_proj only, K=16) ----------------
__global__ __launch_bounds__(256)
void gemm_kernel_sp(const float* __restrict__ A, int lda,
                    const float* __restrict__ W, const float* __restrict__ bias,
                    float* __restrict__ C, int N, int K)
{
    __shared__ float As[16][132];
    __shared__ float Bs[16][132];
    const int tid = threadIdx.x;
    const int tx = tid & 15, ty = tid >> 4;
    const int rowBase = blockIdx.y * 128, colBase = blockIdx.x * 128;
    const int r = tid >> 2, c4 = tid & 3;
    float acc[8][8];
    #pragma unroll
    for (int i = 0; i < 8; i++) {
        #pragma unroll
        for (int j = 0; j < 8; j++) acc[i][j] = 0.f;
    }
    for (int kt = 0; kt < K; kt += 16) {
        #pragma unroll
        for (int rr = r; rr < 128; rr += 64) {
            float4 va = *reinterpret_cast<const float4*>(&A[(size_t)(rowBase + rr) * lda + kt + c4 * 4]);
            As[c4*4+0][rr] = va.x; As[c4*4+1][rr] = va.y; As[c4*4+2][rr] = va.z; As[c4*4+3][rr] = va.w;
            float4 vb = *reinterpret_cast<const float4*>(&W[(size_t)(colBase + rr) * K + kt + c4 * 4]);
            Bs[c4*4+0][rr] = vb.x; Bs[c4*4+1][rr] = vb.y; Bs[c4*4+2][rr] = vb.z; Bs[c4*4+3][rr] = vb.w;
        }
        __syncthreads();
        #pragma unroll
        for (int k = 0; k < 16; k++) {
            float a8[8], b8[8];
            #pragma unroll
            for (int i = 0; i < 8; i++) a8[i] = As[k][ty * 8 + i];
            #pragma unroll
            for (int j = 0; j < 8; j++) b8[j] = Bs[k][tx * 8 + j];
            #pragma unroll
            for (int i = 0; i < 8; i++)
                #pragma unroll
                for (int j = 0; j < 8; j++) acc[i][j] = fmaf(a8[i], b8[j], acc[i][j]);
        }
        __syncthreads();
    }
    #pragma unroll
    for (int i = 0; i < 8; i++) {
        const int row = rowBase + ty * 8 + i;
        #pragma unroll
        for (int j = 0; j < 8; j++) {
            const int col = colBase + tx * 8 + j;
            C[(size_t)row * N + col] = softplusf(acc[i][j] + bias[col]);
        }
    }
}

// ---------------- causal depthwise conv (4 taps) + silu, dual write ----------------
__global__ __launch_bounds__(256)
void conv_silu_kernel(const float* __restrict__ xz, const float* __restrict__ cw,
                      const float* __restrict__ cb, float* __restrict__ xc,
                      __nv_bfloat16* __restrict__ xcb)
{
    const int idx = blockIdx.x * blockDim.x + threadIdx.x;
    const int d = idx & (DIN - 1);
    const int t = idx >> 9;
    const int l = t & (LL - 1);
    const float w0 = cw[d*4+0], w1 = cw[d*4+1], w2 = cw[d*4+2], w3 = cw[d*4+3];
    const float* p = xz + (size_t)t * (2 * DIN) + d;
    float acc = cb[d] + w3 * p[0];
    if (l >= 1) acc = fmaf(w2, p[-(2*DIN)],   acc);
    if (l >= 2) acc = fmaf(w1, p[-2*(2*DIN)], acc);
    if (l >= 3) acc = fmaf(w0, p[-3*(2*DIN)], acc);
    const float v = siluf(acc);
    xc[idx]  = v;
    xcb[idx] = __float2bfloat16(v);
}

// ---------------- selective scan + D skip + silu(z) gate -> bf16 ----------------
__global__ __launch_bounds__(256)
void scan_kernel(const float* __restrict__ dt, const float* __restrict__ xdbl,
                 const float* __restrict__ xc, const float* __restrict__ xz,
                 const float* __restrict__ A_log, const float* __restrict__ D_ssm,
                 __nv_bfloat16* __restrict__ yg)
{
    const int lane   = threadIdx.x & 31;
    const int n      = lane & 15;
    const int warp_g = (blockIdx.x * blockDim.x + threadIdx.x) >> 5;
    const int ch     = warp_g * 2 + (lane >> 4);
    const int b = ch >> 9, d = ch & (DIN - 1);

    const float Aval = -expf(A_log[d * NSS + n]);
    const float Dv   = D_ssm[d];
    float h = 0.f;
    size_t t = (size_t)b * LL;
    for (int l = 0; l < LL; l++, t++) {
        const float dtv = dt[t * DIN + d];
        const float xv  = xc[t * DIN + d];
        const float Bv  = xdbl[t * 64 + DTR_ + n];
        const float Cv  = xdbl[t * 64 + DTR_ + NSS + n];
        const float dA  = __expf(dtv * Aval);
        h = fmaf(dA, h, dtv * Bv * xv);
        float p = h * Cv;
        p += __shfl_xor_sync(0xffffffffu, p, 8);
        p += __shfl_xor_sync(0xffffffffu, p, 4);
        p += __shfl_xor_sync(0xffffffffu, p, 2);
        p += __shfl_xor_sync(0xffffffffu, p, 1);
        if (n == 0) {
            const float y  = p + xv * Dv;
            const float zv = xz[t * (2 * DIN) + DIN + d];
            yg[t * DIN + d] = __float2bfloat16(y * siluf(zv));
        }
    }
}

// ---------------- fused residual-add + LayerNorm, optional bf16 dual write ----------------
__global__ __launch_bounds__(256)
void ln_add_kernel(const float* __restrict__ a, const float* __restrict__ badd,
                   const float* __restrict__ g, const float* __restrict__ beta,
                   float* __restrict__ out, __nv_bfloat16* __restrict__ outb)
{
    const int row = blockIdx.x;
    const int tid = threadIdx.x;
    const float v = a[(size_t)row * DD + tid] + badd[(size_t)row * DD + tid];
    float s = v, s2 = v * v;
    #pragma unroll
    for (int m = 16; m > 0; m >>= 1) {
        s  += __shfl_xor_sync(0xffffffffu, s,  m);
        s2 += __shfl_xor_sync(0xffffffffu, s2, m);
    }
    __shared__ float sh[8], sh2[8];
    if ((tid & 31) == 0) { sh[tid >> 5] = s; sh2[tid >> 5] = s2; }
    __syncthreads();
    float ts = 0.f, ts2 = 0.f;
    #pragma unroll
    for (int i = 0; i < 8; i++) { ts += sh[i]; ts2 += sh2[i]; }
    const float mean = ts * (1.f / DD);
    const float var  = ts2 * (1.f / DD) - mean * mean;
    const float inv  = rsqrtf(var + 1e-5f);
    const float o = (v - mean) * inv * g[tid] + beta[tid];
    out[(size_t)row * DD + tid] = o;
    if (outb) outb[(size_t)row * DD + tid] = __float2bfloat16(o);
}

// ---------------- launch ----------------
extern "C" void kernel_launch(void* const* d_in, const int* in_sizes, int n_in,
                              void* d_out, int out_size)
{
    const float* x          = (const float*)d_in[0];
    const float* in_proj_w  = (const float*)d_in[1];
    const float* in_proj_b  = (const float*)d_in[2];
    const float* conv_w     = (const float*)d_in[3];
    const float* conv_b     = (const float*)d_in[4];
    const float* x_proj_w   = (const float*)d_in[5];
    const float* dt_proj_w  = (const float*)d_in[6];
    const float* dt_proj_b  = (const float*)d_in[7];
    const float* A_log      = (const float*)d_in[8];
    const float* D_ssm      = (const float*)d_in[9];
    const float* out_proj_w = (const float*)d_in[10];
    const float* out_proj_b = (const float*)d_in[11];
    const float* ln1_g      = (const float*)d_in[12];
    const float* ln1_b      = (const float*)d_in[13];
    const float* fc1_w      = (const float*)d_in[14];
    const float* fc1_b      = (const float*)d_in[15];
    const float* fc2_w      = (const float*)d_in[16];
    const float* fc2_b      = (const float*)d_in[17];
    const float* ln2_g      = (const float*)d_in[18];
    const float* ln2_b      = (const float*)d_in[19];
    float* out = (float*)d_out;

    float *xz, *xconv, *xdbl, *dtb, *ssm, *y1, *f2, *zero;
    __nv_bfloat16 *xconvb, *ygb, *y1b, *h1b, *xb, *w_in, *w_xp, *w_out, *w_fc1, *w_fc2;
    cudaGetSymbolAddress((void**)&xz,     g_xz);
    cudaGetSymbolAddress((void**)&xconv,  g_xconv);
    cudaGetSymbolAddress((void**)&xconvb, g_xconvb);
    cudaGetSymbolAddress((void**)&xdbl,   g_xdbl);
    cudaGetSymbolAddress((void**)&dtb,    g_dt);
    cudaGetSymbolAddress((void**)&ygb,    g_ygb);
    cudaGetSymbolAddress((void**)&ssm,    g_ssm);
    cudaGetSymbolAddress((void**)&y1,     g_y1);
    cudaGetSymbolAddress((void**)&y1b,    g_y1b);
    cudaGetSymbolAddress((void**)&h1b,    g_h1b);
    cudaGetSymbolAddress((void**)&f2,     g_f2);
    cudaGetSymbolAddress((void**)&xb,     g_xb);
    cudaGetSymbolAddress((void**)&w_in,   g_w_in);
    cudaGetSymbolAddress((void**)&w_xp,   g_w_xp);
    cudaGetSymbolAddress((void**)&w_out,  g_w_out);
    cudaGetSymbolAddress((void**)&w_fc1,  g_w_fc1);
    cudaGetSymbolAddress((void**)&w_fc2,  g_w_fc2);
    cudaGetSymbolAddress((void**)&zero,   g_zero);

    // ---- convert inputs/weights to bf16 ----
    cvt_bf16_kernel<<<(TOK*DD+255)/256, 256>>>(x, xb, TOK*DD);
    cvt_bf16_kernel<<<(2*DIN*DD+255)/256, 256>>>(in_proj_w, w_in, 2*DIN*DD);
    pad_xprojw_kernel<<<(64*DIN+255)/256, 256>>>(x_proj_w, w_xp);
    cvt_bf16_kernel<<<(DD*DIN+255)/256, 256>>>(out_proj_w, w_out, DD*DIN);
    cvt_bf16_kernel<<<(DFF_*DD+255)/256, 256>>>(fc1_w, w_fc1, DFF_*DD);
    cvt_bf16_kernel<<<(DD*DFF_+255)/256, 256>>>(fc2_w, w_fc2, DD*DFF_);

    // 1) in_proj: [8192,256] @ [1024,256]^T -> xz fp32
    mma_gemm<128,0,0><<<dim3(2*DIN/128, TOK/128), 256>>>(xb, w_in, in_proj_b, xz, 2*DIN, DD);
    // 2) conv + silu (fp32 + bf16)
    conv_silu_kernel<<<(TOK*DIN)/256, 256>>>(xz, conv_w, conv_b, xconv, xconvb);
    // 3) x_proj: [8192,512] @ [64,512]^T -> xdbl fp32 (cols 48..63 zero)
    mma_gemm<64,0,0><<<dim3(1, TOK/128), 256>>>(xconvb, w_xp, zero, xdbl, 64, DIN);
    // 4) dt_proj + softplus (SIMT, K=16)
    gemm_kernel_sp<<<dim3(DIN/128, TOK/128), 256>>>(xdbl, 64, dt_proj_w, dt_proj_b, dtb, DIN, DTR_);
    // 5) selective scan + gate -> bf16
    scan_kernel<<<(BB*DIN)/16, 256>>>(dtb, xdbl, xconv, xz, A_log, D_ssm, ygb);
    // 6) out_proj: [8192,512] @ [256,512]^T -> ssm fp32
    mma_gemm<128,0,0><<<dim3(DD/128, TOK/128), 256>>>(ygb, w_out, out_proj_b, ssm, DD, DIN);
    // 7) LN1(x + ssm) -> y1 fp32 + y1b bf16
    ln_add_kernel<<<TOK, 256>>>(x, ssm, ln1_g, ln1_b, y1, y1b);
    // 8) fc1 + gelu -> h1b bf16
    mma_gemm<128,1,1><<<dim3(DFF_/128, TOK/128), 256>>>(y1b, w_fc1, fc1_b, h1b, DFF_, DD);
    // 9) fc2 + gelu -> f2 fp32
    mma_gemm<128,1,0><<<dim3(DD/128, TOK/128), 256>>>(h1b, w_fc2, fc2_b, f2, DD, DFF_);
    // 10) LN2(y1 + ffn) -> out
    ln_add_kernel<<<TOK, 256>>>(y1, f2, ln2_g, ln2_b, out, (__nv_bfloat16*)0);
}

// round 5
// speedup vs baseline: 4.9947x; 3.7967x over previous
#include <cuda_runtime.h>
#include <cuda_bf16.h>
#include <math.h>
#include <stdint.h>

// Problem constants (fixed shapes)
#define BB   4
#define LL   2048
#define DD   256
#define DIN  512
#define NSS  16
#define DTR_ 16
#define DFF_ 1024
#define TOK  (BB*LL)      // 8192

// ---------------- scratch (static device memory) ----------------
__device__ float          g_xz    [TOK * 2 * DIN];
__device__ float          g_xcT   [TOK * DIN];        // silu(conv), channel-major [b*512+d][2048]
__device__ float          g_zsT   [TOK * DIN];        // silu(z), channel-major
__device__ __nv_bfloat16  g_xconvb[TOK * DIN];        // silu(conv) bf16 token-major
__device__ float          g_xdbl  [TOK * 64];         // dt(16)|B(16)|C(16)|pad(16)
__device__ float          g_dtT   [TOK * DIN];        // softplus(dt_proj), channel-major
__device__ __nv_bfloat16  g_ygb   [TOK * DIN];
__device__ float          g_ssm   [TOK * DD];
__device__ float          g_y1    [TOK * DD];
__device__ __nv_bfloat16  g_y1b   [TOK * DD];
__device__ __nv_bfloat16  g_h1b   [TOK * DFF_];
__device__ float          g_f2    [TOK * DD];
__device__ __nv_bfloat16  g_xb    [TOK * DD];
__device__ __nv_bfloat16  g_w_in  [2 * DIN * DD];
__device__ __nv_bfloat16  g_w_xp  [64 * DIN];
__device__ __nv_bfloat16  g_w_out [DD * DIN];
__device__ __nv_bfloat16  g_w_fc1 [DFF_ * DD];
__device__ __nv_bfloat16  g_w_fc2 [DD * DFF_];
__device__ float          g_zero  [64];

// ---------------- math helpers ----------------
__device__ __forceinline__ float siluf(float v)     { return v / (1.f + __expf(-v)); }
__device__ __forceinline__ float geluf(float v)     { return 0.5f * v * (1.f + erff(v * 0.70710678118654752f)); }
__device__ __forceinline__ float softplusf(float v) { return fmaxf(v, 0.f) + log1pf(__expf(-fabsf(v))); }

__device__ __forceinline__ uint32_t smem_u32(const void* p) {
    uint32_t a;
    asm("{ .reg .u64 t; cvta.to.shared.u64 t, %1; cvt.u32.u64 %0, t; }" : "=r"(a) : "l"(p));
    return a;
}
__device__ __forceinline__ void ldsm4(uint32_t& r0, uint32_t& r1, uint32_t& r2, uint32_t& r3, uint32_t addr) {
    asm volatile("ldmatrix.sync.aligned.m8n8.x4.shared.b16 {%0,%1,%2,%3}, [%4];"
                 : "=r"(r0), "=r"(r1), "=r"(r2), "=r"(r3) : "r"(addr));
}
__device__ __forceinline__ void mma16816(float* c, const uint32_t* a, const uint32_t* b) {
    asm volatile("mma.sync.aligned.m16n8k16.row.col.f32.bf16.bf16.f32 "
                 "{%0,%1,%2,%3},{%4,%5,%6,%7},{%8,%9},{%0,%1,%2,%3};"
                 : "+f"(c[0]), "+f"(c[1]), "+f"(c[2]), "+f"(c[3])
                 : "r"(a[0]), "r"(a[1]), "r"(a[2]), "r"(a[3]), "r"(b[0]), "r"(b[1]));
}
__device__ __forceinline__ void cp16(uint32_t dst, const void* src) {
    asm volatile("cp.async.cg.shared.global [%0], [%1], 16;" :: "r"(dst), "l"(src));
}
#define CP_COMMIT() asm volatile("cp.async.commit_group;" ::: "memory")

// =======================================================================
// SM80-style pipelined bf16 GEMM (unchanged from round 4, passing)
// =======================================================================
template<int BN, int EPI, int OUTT>
__global__ __launch_bounds__(256)
void mma_gemm(const __nv_bfloat16* __restrict__ A, const __nv_bfloat16* __restrict__ W,
              const float* __restrict__ bias, void* __restrict__ C, int N, int K)
{
    constexpr int BM  = 128;
    constexpr int BK  = 32;
    constexpr int AST = 40;
    constexpr int NT  = BN / 32;

    __shared__ __align__(16) __nv_bfloat16 sA[2][BM * AST];
    __shared__ __align__(16) __nv_bfloat16 sB[2][BN * AST];

    const int tid  = threadIdx.x;
    const int wid  = tid >> 5;
    const int lane = tid & 31;
    const int warp_m = wid & 1;
    const int warp_n = wid >> 1;
    const int rowBase = blockIdx.y * BM;
    const int colBase = blockIdx.x * BN;
    const int NK = K >> 5;

    auto prefetch = [&](int s, int kc) {
        #pragma unroll
        for (int i = 0; i < 2; i++) {
            const int cidx = i * 256 + tid;
            const int row = cidx >> 2, c4 = cidx & 3;
            cp16(smem_u32(&sA[s][row * AST + c4 * 8]),
                 A + (size_t)(rowBase + row) * K + kc * BK + c4 * 8);
        }
        #pragma unroll
        for (int i = 0; i < BN / 64; i++) {
            const int cidx = i * 256 + tid;
            const int row = cidx >> 2, c4 = cidx & 3;
            cp16(smem_u32(&sB[s][row * AST + c4 * 8]),
                 W + (size_t)(colBase + row) * K + kc * BK + c4 * 8);
        }
    };

    float acc[4][NT][4];
    #pragma unroll
    for (int mi = 0; mi < 4; mi++)
        #pragma unroll
        for (int ni = 0; ni < NT; ni++)
            #pragma unroll
            for (int r = 0; r < 4; r++) acc[mi][ni][r] = 0.f;

    prefetch(0, 0);
    CP_COMMIT();

    for (int kt = 0; kt < NK; kt++) {
        if (kt + 1 < NK) {
            prefetch((kt + 1) & 1, kt + 1);
            CP_COMMIT();
            asm volatile("cp.async.wait_group 1;" ::: "memory");
        } else {
            asm volatile("cp.async.wait_group 0;" ::: "memory");
        }
        __syncthreads();

        const int s = kt & 1;
        #pragma unroll
        for (int k = 0; k < 2; k++) {
            uint32_t af[4][4];
            #pragma unroll
            for (int mi = 0; mi < 4; mi++) {
                const int row = warp_m * 64 + mi * 16 + (lane & 15);
                const int col = k * 16 + (lane >> 4) * 8;
                ldsm4(af[mi][0], af[mi][1], af[mi][2], af[mi][3],
                      smem_u32(&sA[s][row * AST + col]));
            }
            uint32_t bf[NT][2];
            #pragma unroll
            for (int np = 0; np < NT / 2; np++) {
                const int n0 = warp_n * (NT * 8) + np * 16;
                const int q  = lane >> 3;
                const int row = n0 + (q & 1) * 8 + (lane & 7);
                const int col = k * 16 + (q >> 1) * 8;
                uint32_t r0, r1, r2, r3;
                ldsm4(r0, r1, r2, r3, smem_u32(&sB[s][row * AST + col]));
                bf[np*2][0] = r0; bf[np*2+1][0] = r1;
                bf[np*2][1] = r2; bf[np*2+1][1] = r3;
            }
            #pragma unroll
            for (int mi = 0; mi < 4; mi++)
                #pragma unroll
                for (int ni = 0; ni < NT; ni++)
                    mma16816(acc[mi][ni], af[mi], bf[ni]);
        }
        __syncthreads();
    }

    const int g  = lane >> 2;
    const int c2 = (lane & 3) * 2;
    #pragma unroll
    for (int mi = 0; mi < 4; mi++) {
        const int row0 = rowBase + warp_m * 64 + mi * 16 + g;
        #pragma unroll
        for (int ni = 0; ni < NT; ni++) {
            const int col = colBase + warp_n * (NT * 8) + ni * 8 + c2;
            const float b0 = bias[col], b1 = bias[col + 1];
            float v00 = acc[mi][ni][0] + b0, v01 = acc[mi][ni][1] + b1;
            float v10 = acc[mi][ni][2] + b0, v11 = acc[mi][ni][3] + b1;
            if (EPI == 1) { v00 = geluf(v00); v01 = geluf(v01); v10 = geluf(v10); v11 = geluf(v11); }
            if (OUTT == 0) {
                *(float2*)((float*)C + (size_t)row0 * N + col)       = make_float2(v00, v01);
                *(float2*)((float*)C + (size_t)(row0 + 8) * N + col) = make_float2(v10, v11);
            } else {
                __nv_bfloat16* Cb = (__nv_bfloat16*)C;
                *(__nv_bfloat162*)(Cb + (size_t)row0 * N + col)       = __float22bfloat162_rn(make_float2(v00, v01));
                *(__nv_bfloat162*)(Cb + (size_t)(row0 + 8) * N + col) = __float22bfloat162_rn(make_float2(v10, v11));
            }
        }
    }
}

// ---------------- fp32 -> bf16 converters ----------------
__global__ void cvt_bf16_kernel(const float* __restrict__ in, __nv_bfloat16* __restrict__ out, int n)
{
    int i = blockIdx.x * blockDim.x + threadIdx.x;
    if (i < n) out[i] = __float2bfloat16(in[i]);
}
__global__ void pad_xprojw_kernel(const float* __restrict__ W, __nv_bfloat16* __restrict__ out)
{
    int i = blockIdx.x * blockDim.x + threadIdx.x;      // 64*512
    int r = i >> 9, k = i & 511;
    out[i] = __float2bfloat16(r < 48 ? W[r * 512 + k] : 0.f);
}

// ---------------- SIMT SGEMM for dt_proj (K=16), writes softplus -> dtT channel-major ----
__global__ __launch_bounds__(256)
void gemm_kernel_sp(const float* __restrict__ A, int lda,
                    const float* __restrict__ W, const float* __restrict__ bias,
                    float* __restrict__ dtT, int N, int K)
{
    __shared__ float As[16][132];
    __shared__ float Bs[16][132];
    const int tid = threadIdx.x;
    const int tx = tid & 15, ty = tid >> 4;
    const int rowBase = blockIdx.y * 128, colBase = blockIdx.x * 128;
    const int r = tid >> 2, c4 = tid & 3;
    float acc[8][8];
    #pragma unroll
    for (int i = 0; i < 8; i++) {
        #pragma unroll
        for (int j = 0; j < 8; j++) acc[i][j] = 0.f;
    }
    for (int kt = 0; kt < K; kt += 16) {
        #pragma unroll
        for (int rr = r; rr < 128; rr += 64) {
            float4 va = *reinterpret_cast<const float4*>(&A[(size_t)(rowBase + rr) * lda + kt + c4 * 4]);
            As[c4*4+0][rr] = va.x; As[c4*4+1][rr] = va.y; As[c4*4+2][rr] = va.z; As[c4*4+3][rr] = va.w;
            float4 vb = *reinterpret_cast<const float4*>(&W[(size_t)(colBase + rr) * K + kt + c4 * 4]);
            Bs[c4*4+0][rr] = vb.x; Bs[c4*4+1][rr] = vb.y; Bs[c4*4+2][rr] = vb.z; Bs[c4*4+3][rr] = vb.w;
        }
        __syncthreads();
        #pragma unroll
        for (int k = 0; k < 16; k++) {
            float a8[8], b8[8];
            #pragma unroll
            for (int i = 0; i < 8; i++) a8[i] = As[k][ty * 8 + i];
            #pragma unroll
            for (int j = 0; j < 8; j++) b8[j] = Bs[k][tx * 8 + j];
            #pragma unroll
            for (int i = 0; i < 8; i++)
                #pragma unroll
                for (int j = 0; j < 8; j++) acc[i][j] = fmaf(a8[i], b8[j], acc[i][j]);
        }
        __syncthreads();
    }
    // epilogue: softplus, store channel-major dtT[(b*512+d)][l], 8 consecutive l per thread
    const int t0 = rowBase + ty * 8;      // rows are consecutive tokens
    const int b  = t0 >> 11;
    const int l  = t0 & 2047;
    #pragma unroll
    for (int j = 0; j < 8; j++) {
        const int col = colBase + tx * 8 + j;
        const float bj = bias[col];
        float v[8];
        #pragma unroll
        for (int i = 0; i < 8; i++) v[i] = softplusf(acc[i][j] + bj);
        float* o = dtT + ((size_t)(b * DIN + col)) * LL + l;
        *(float4*)(o)     = make_float4(v[0], v[1], v[2], v[3]);
        *(float4*)(o + 4) = make_float4(v[4], v[5], v[6], v[7]);
    }
}

// ---------------- conv+silu with transpose: xcT/zsT channel-major + xconvb token-major ----
__global__ __launch_bounds__(256)
void conv_silu_tr(const float* __restrict__ xz, const float* __restrict__ cw,
                  const float* __restrict__ cb, __nv_bfloat16* __restrict__ xconvb,
                  float* __restrict__ xcT, float* __restrict__ zsT)
{
    __shared__ float sxi[35][33];
    __shared__ float sout[32][33];
    __shared__ float sz[32][33];
    const int l0 = blockIdx.x * 32;
    const int d0 = blockIdx.y * 32;
    const int b  = blockIdx.z;
    const int tid = threadIdx.x;

    for (int i = tid; i < 35 * 32; i += 256) {
        const int r = i >> 5, c = i & 31;
        const int l = l0 - 3 + r;
        sxi[r][c] = (l >= 0) ? xz[((size_t)(b * LL + l)) * (2 * DIN) + d0 + c] : 0.f;
    }
    for (int i = tid; i < 32 * 32; i += 256) {
        const int r = i >> 5, c = i & 31;
        sz[r][c] = xz[((size_t)(b * LL + l0 + r)) * (2 * DIN) + DIN + d0 + c];
    }
    __syncthreads();
    for (int i = tid; i < 32 * 32; i += 256) {
        const int l = i >> 5, c = i & 31;
        const int d = d0 + c;
        float v = cb[d] + cw[d*4+3] * sxi[l+3][c] + cw[d*4+2] * sxi[l+2][c]
                        + cw[d*4+1] * sxi[l+1][c] + cw[d*4+0] * sxi[l][c];
        v = siluf(v);
        sout[l][c] = v;
        xconvb[((size_t)(b * LL + l0 + l)) * DIN + d] = __float2bfloat16(v);
    }
    __syncthreads();
    for (int i = tid; i < 32 * 32; i += 256) {
        const int c = i >> 5, l = i & 31;    // l fast -> coalesced along time
        const size_t o = ((size_t)(b * DIN + d0 + c)) * LL + l0 + l;
        xcT[o] = sout[l][c];
        zsT[o] = siluf(sz[l][c]);
    }
}

// ---------------- selective scan: channel-major inputs, B/C staged via cp.async ----------
// Block = 8 warps = 16 channels, all same batch b. Half-warp = one channel, lanes = 16 states.
__global__ __launch_bounds__(256)
void scan_kernel(const float* __restrict__ dtT, const float* __restrict__ xdbl,
                 const float* __restrict__ xcT, const float* __restrict__ zsT,
                 const float* __restrict__ A_log, const float* __restrict__ D_ssm,
                 __nv_bfloat16* __restrict__ yg)
{
    __shared__ __align__(16) float buf[2][64][32];   // [stage][t_local][B(16)|C(16)]
    const int tid  = threadIdx.x;
    const int lane = tid & 31;
    const int n    = lane & 15;
    const int hw   = lane >> 4;
    const int w    = tid >> 5;
    const int ch   = blockIdx.x * 16 + w * 2 + hw;   // 0..2047, same b within block
    const int b    = ch >> 9, d = ch & (DIN - 1);

    const float Aval = -expf(A_log[d * NSS + n]);
    const float Dv   = D_ssm[d];
    const float* dtp = dtT + (size_t)ch * LL;
    const float* xcp = xcT + (size_t)ch * LL;
    const float* zp  = zsT + (size_t)ch * LL;
    const float* xrow = xdbl + (size_t)b * LL * 64;

    auto fill = [&](int tile, int s) {
        #pragma unroll
        for (int i = 0; i < 2; i++) {                // 512 chunks of 16B (floats 16..47 per row)
            const int idx = i * 256 + tid;
            const int r = idx >> 3, c = idx & 7;
            cp16(smem_u32(&buf[s][r][c * 4]), xrow + ((size_t)(tile * 64 + r)) * 64 + 16 + c * 4);
        }
    };
    fill(0, 0); CP_COMMIT();
    fill(1, 1); CP_COMMIT();

    float h = 0.f;
    for (int tile = 0; tile < LL / 64; tile++) {
        if (tile < LL / 64 - 1) asm volatile("cp.async.wait_group 1;" ::: "memory");
        else                    asm volatile("cp.async.wait_group 0;" ::: "memory");
        __syncthreads();
        const int s = tile & 1;
        const int lbase = tile * 64;
        #pragma unroll 4
        for (int j = 0; j < 64; j++) {
            const int l = lbase + j;
            const float dtv = dtp[l];
            const float xv  = xcp[l];
            const float Bv  = buf[s][j][n];
            const float Cv  = buf[s][j][16 + n];
            const float dA  = __expf(dtv * Aval);
            h = fmaf(dA, h, dtv * Bv * xv);
            float p = h * Cv;
            p += __shfl_xor_sync(0xffffffffu, p, 8);
            p += __shfl_xor_sync(0xffffffffu, p, 4);
            p += __shfl_xor_sync(0xffffffffu, p, 2);
            p += __shfl_xor_sync(0xffffffffu, p, 1);
            if (n == 0) {
                const float y = p + xv * Dv;
                yg[((size_t)(b * LL + l)) * DIN + d] = __float2bfloat16(y * zp[l]);
            }
        }
        __syncthreads();
        if (tile + 2 < LL / 64) { fill(tile + 2, s); CP_COMMIT(); }
    }
}

// ---------------- fused residual-add + LayerNorm, optional bf16 dual write ----------------
__global__ __launch_bounds__(256)
void ln_add_kernel(const float* __restrict__ a, const float* __restrict__ badd,
                   const float* __restrict__ g, const float* __restrict__ beta,
                   float* __restrict__ out, __nv_bfloat16* __restrict__ outb)
{
    const int row = blockIdx.x;
    const int tid = threadIdx.x;
    const float v = a[(size_t)row * DD + tid] + badd[(size_t)row * DD + tid];
    float s = v, s2 = v * v;
    #pragma unroll
    for (int m = 16; m > 0; m >>= 1) {
        s  += __shfl_xor_sync(0xffffffffu, s,  m);
        s2 += __shfl_xor_sync(0xffffffffu, s2, m);
    }
    __shared__ float sh[8], sh2[8];
    if ((tid & 31) == 0) { sh[tid >> 5] = s; sh2[tid >> 5] = s2; }
    __syncthreads();
    float ts = 0.f, ts2 = 0.f;
    #pragma unroll
    for (int i = 0; i < 8; i++) { ts += sh[i]; ts2 += sh2[i]; }
    const float mean = ts * (1.f / DD);
    const float var  = ts2 * (1.f / DD) - mean * mean;
    const float inv  = rsqrtf(var + 1e-5f);
    const float o = (v - mean) * inv * g[tid] + beta[tid];
    out[(size_t)row * DD + tid] = o;
    if (outb) outb[(size_t)row * DD + tid] = __float2bfloat16(o);
}

// ---------------- launch ----------------
extern "C" void kernel_launch(void* const* d_in, const int* in_sizes, int n_in,
                              void* d_out, int out_size)
{
    const float* x          = (const float*)d_in[0];
    const float* in_proj_w  = (const float*)d_in[1];
    const float* in_proj_b  = (const float*)d_in[2];
    const float* conv_w     = (const float*)d_in[3];
    const float* conv_b     = (const float*)d_in[4];
    const float* x_proj_w   = (const float*)d_in[5];
    const float* dt_proj_w  = (const float*)d_in[6];
    const float* dt_proj_b  = (const float*)d_in[7];
    const float* A_log      = (const float*)d_in[8];
    const float* D_ssm      = (const float*)d_in[9];
    const float* out_proj_w = (const float*)d_in[10];
    const float* out_proj_b = (const float*)d_in[11];
    const float* ln1_g      = (const float*)d_in[12];
    const float* ln1_b      = (const float*)d_in[13];
    const float* fc1_w      = (const float*)d_in[14];
    const float* fc1_b      = (const float*)d_in[15];
    const float* fc2_w      = (const float*)d_in[16];
    const float* fc2_b      = (const float*)d_in[17];
    const float* ln2_g      = (const float*)d_in[18];
    const float* ln2_b      = (const float*)d_in[19];
    float* out = (float*)d_out;

    float *xz, *xcT, *zsT, *xdbl, *dtT, *ssm, *y1, *f2, *zero;
    __nv_bfloat16 *xconvb, *ygb, *y1b, *h1b, *xb, *w_in, *w_xp, *w_out, *w_fc1, *w_fc2;
    cudaGetSymbolAddress((void**)&xz,     g_xz);
    cudaGetSymbolAddress((void**)&xcT,    g_xcT);
    cudaGetSymbolAddress((void**)&zsT,    g_zsT);
    cudaGetSymbolAddress((void**)&xconvb, g_xconvb);
    cudaGetSymbolAddress((void**)&xdbl,   g_xdbl);
    cudaGetSymbolAddress((void**)&dtT,    g_dtT);
    cudaGetSymbolAddress((void**)&ygb,    g_ygb);
    cudaGetSymbolAddress((void**)&ssm,    g_ssm);
    cudaGetSymbolAddress((void**)&y1,     g_y1);
    cudaGetSymbolAddress((void**)&y1b,    g_y1b);
    cudaGetSymbolAddress((void**)&h1b,    g_h1b);
    cudaGetSymbolAddress((void**)&f2,     g_f2);
    cudaGetSymbolAddress((void**)&xb,     g_xb);
    cudaGetSymbolAddress((void**)&w_in,   g_w_in);
    cudaGetSymbolAddress((void**)&w_xp,   g_w_xp);
    cudaGetSymbolAddress((void**)&w_out,  g_w_out);
    cudaGetSymbolAddress((void**)&w_fc1,  g_w_fc1);
    cudaGetSymbolAddress((void**)&w_fc2,  g_w_fc2);
    cudaGetSymbolAddress((void**)&zero,   g_zero);

    // 0,1) input/weight conversion for in_proj
    cvt_bf16_kernel<<<(TOK*DD+255)/256, 256>>>(x, xb, TOK*DD);
    cvt_bf16_kernel<<<(2*DIN*DD+255)/256, 256>>>(in_proj_w, w_in, 2*DIN*DD);
    // 2) in_proj GEMM -> xz fp32
    mma_gemm<128,0,0><<<dim3(2*DIN/128, TOK/128), 256>>>(xb, w_in, in_proj_b, xz, 2*DIN, DD);
    // 3) conv + silu + transpose -> xcT, zsT (channel-major), xconvb (token-major bf16)
    conv_silu_tr<<<dim3(LL/32, DIN/32, BB), 256>>>(xz, conv_w, conv_b, xconvb, xcT, zsT);
    // 4) pad x_proj weights
    pad_xprojw_kernel<<<(64*DIN+255)/256, 256>>>(x_proj_w, w_xp);
    // 5) x_proj GEMM (ncu capture target) -> xdbl
    mma_gemm<64,0,0><<<dim3(1, TOK/128), 256>>>(xconvb, w_xp, zero, xdbl, 64, DIN);
    // 6) dt_proj + softplus -> dtT channel-major
    gemm_kernel_sp<<<dim3(DIN/128, TOK/128), 256>>>(xdbl, 64, dt_proj_w, dt_proj_b, dtT, DIN, DTR_);
    // 7) selective scan -> ygb token-major bf16
    scan_kernel<<<(BB*DIN)/16, 256>>>(dtT, xdbl, xcT, zsT, A_log, D_ssm, ygb);
    // 8) out_proj weight conversion
    cvt_bf16_kernel<<<(DD*DIN+255)/256, 256>>>(out_proj_w, w_out, DD*DIN);
    // 9) out_proj GEMM -> ssm
    mma_gemm<128,0,0><<<dim3(DD/128, TOK/128), 256>>>(ygb, w_out, out_proj_b, ssm, DD, DIN);
    // 10) LN1(x + ssm)
    ln_add_kernel<<<TOK, 256>>>(x, ssm, ln1_g, ln1_b, y1, y1b);
    // 11,12) fc1 + gelu
    cvt_bf16_kernel<<<(DFF_*DD+255)/256, 256>>>(fc1_w, w_fc1, DFF_*DD);
    mma_gemm<128,1,1><<<dim3(DFF_/128, TOK/128), 256>>>(y1b, w_fc1, fc1_b, h1b, DFF_, DD);
    // 13,14) fc2 + gelu
    cvt_bf16_kernel<<<(DD*DFF_+255)/256, 256>>>(fc2_w, w_fc2, DD*DFF_);
    mma_gemm<128,1,0><<<dim3(DD/128, TOK/128), 256>>>(h1b, w_fc2, fc2_b, f2, DD, DFF_);
    // 15) LN2(y1 + ffn) -> out
    ln_add_kernel<<<TOK, 256>>>(y1, f2, ln2_g, ln2_b, out, (__nv_bfloat16*)0);
}

// round 6
// speedup vs baseline: 6.9823x; 1.3980x over previous
#include <cuda_runtime.h>
#include <cuda_bf16.h>
#include <math.h>
#include <stdint.h>

// Problem constants (fixed shapes)
#define BB   4
#define LL   2048
#define DD   256
#define DIN  512
#define NSS  16
#define DTR_ 16
#define DFF_ 1024
#define TOK  (BB*LL)      // 8192
#define NCH  (BB*DIN)     // 2048 scan channels
#define GCH  16           // scan chunks
#define CL   (LL/GCH)     // 128 steps per chunk

// ---------------- scratch (static device memory) ----------------
__device__ float          g_xz    [TOK * 2 * DIN];
__device__ float          g_xcT   [TOK * DIN];        // silu(conv), channel-major [b*512+d][2048]
__device__ float          g_zsT   [TOK * DIN];        // silu(z), channel-major
__device__ __nv_bfloat16  g_xconvb[TOK * DIN];        // silu(conv) bf16 token-major
__device__ float          g_xdbl  [TOK * 64];         // dt(16)|B(16)|C(16)|pad(16)
__device__ float          g_dtT   [TOK * DIN];        // softplus(dt_proj), channel-major
__device__ float          g_P     [NCH * GCH * NSS];  // chunk products
__device__ float          g_He    [NCH * GCH * NSS];  // chunk terminal states
__device__ float          g_Hin   [NCH * GCH * NSS];  // chunk input states
__device__ __nv_bfloat16  g_ygb   [TOK * DIN];
__device__ float          g_ssm   [TOK * DD];
__device__ float          g_y1    [TOK * DD];
__device__ __nv_bfloat16  g_y1b   [TOK * DD];
__device__ __nv_bfloat16  g_h1b   [TOK * DFF_];
__device__ float          g_f2    [TOK * DD];
__device__ __nv_bfloat16  g_xb    [TOK * DD];
__device__ __nv_bfloat16  g_w_in  [2 * DIN * DD];
__device__ __nv_bfloat16  g_w_xp  [64 * DIN];
__device__ __nv_bfloat16  g_w_out [DD * DIN];
__device__ __nv_bfloat16  g_w_fc1 [DFF_ * DD];
__device__ __nv_bfloat16  g_w_fc2 [DD * DFF_];
__device__ float          g_zero  [64];

// ---------------- math helpers ----------------
__device__ __forceinline__ float siluf(float v)     { return v / (1.f + __expf(-v)); }
__device__ __forceinline__ float geluf(float v)     { return 0.5f * v * (1.f + erff(v * 0.70710678118654752f)); }
__device__ __forceinline__ float softplusf(float v) { return fmaxf(v, 0.f) + log1pf(__expf(-fabsf(v))); }

__device__ __forceinline__ uint32_t smem_u32(const void* p) {
    uint32_t a;
    asm("{ .reg .u64 t; cvta.to.shared.u64 t, %1; cvt.u32.u64 %0, t; }" : "=r"(a) : "l"(p));
    return a;
}
__device__ __forceinline__ void ldsm4(uint32_t& r0, uint32_t& r1, uint32_t& r2, uint32_t& r3, uint32_t addr) {
    asm volatile("ldmatrix.sync.aligned.m8n8.x4.shared.b16 {%0,%1,%2,%3}, [%4];"
                 : "=r"(r0), "=r"(r1), "=r"(r2), "=r"(r3) : "r"(addr));
}
__device__ __forceinline__ void mma16816(float* c, const uint32_t* a, const uint32_t* b) {
    asm volatile("mma.sync.aligned.m16n8k16.row.col.f32.bf16.bf16.f32 "
                 "{%0,%1,%2,%3},{%4,%5,%6,%7},{%8,%9},{%0,%1,%2,%3};"
                 : "+f"(c[0]), "+f"(c[1]), "+f"(c[2]), "+f"(c[3])
                 : "r"(a[0]), "r"(a[1]), "r"(a[2]), "r"(a[3]), "r"(b[0]), "r"(b[1]));
}
__device__ __forceinline__ void cp16(uint32_t dst, const void* src) {
    asm volatile("cp.async.cg.shared.global [%0], [%1], 16;" :: "r"(dst), "l"(src));
}
#define CP_COMMIT() asm volatile("cp.async.commit_group;" ::: "memory")

// =======================================================================
// SM80-style pipelined bf16 GEMM (unchanged — passing, profiled this round)
// =======================================================================
template<int BN, int EPI, int OUTT>
__global__ __launch_bounds__(256)
void mma_gemm(const __nv_bfloat16* __restrict__ A, const __nv_bfloat16* __restrict__ W,
              const float* __restrict__ bias, void* __restrict__ C, int N, int K)
{
    constexpr int BM  = 128;
    constexpr int BK  = 32;
    constexpr int AST = 40;
    constexpr int NT  = BN / 32;

    __shared__ __align__(16) __nv_bfloat16 sA[2][BM * AST];
    __shared__ __align__(16) __nv_bfloat16 sB[2][BN * AST];

    const int tid  = threadIdx.x;
    const int wid  = tid >> 5;
    const int lane = tid & 31;
    const int warp_m = wid & 1;
    const int warp_n = wid >> 1;
    const int rowBase = blockIdx.y * BM;
    const int colBase = blockIdx.x * BN;
    const int NK = K >> 5;

    auto prefetch = [&](int s, int kc) {
        #pragma unroll
        for (int i = 0; i < 2; i++) {
            const int cidx = i * 256 + tid;
            const int row = cidx >> 2, c4 = cidx & 3;
            cp16(smem_u32(&sA[s][row * AST + c4 * 8]),
                 A + (size_t)(rowBase + row) * K + kc * BK + c4 * 8);
        }
        #pragma unroll
        for (int i = 0; i < BN / 64; i++) {
            const int cidx = i * 256 + tid;
            const int row = cidx >> 2, c4 = cidx & 3;
            cp16(smem_u32(&sB[s][row * AST + c4 * 8]),
                 W + (size_t)(colBase + row) * K + kc * BK + c4 * 8);
        }
    };

    float acc[4][NT][4];
    #pragma unroll
    for (int mi = 0; mi < 4; mi++)
        #pragma unroll
        for (int ni = 0; ni < NT; ni++)
            #pragma unroll
            for (int r = 0; r < 4; r++) acc[mi][ni][r] = 0.f;

    prefetch(0, 0);
    CP_COMMIT();

    for (int kt = 0; kt < NK; kt++) {
        if (kt + 1 < NK) {
            prefetch((kt + 1) & 1, kt + 1);
            CP_COMMIT();
            asm volatile("cp.async.wait_group 1;" ::: "memory");
        } else {
            asm volatile("cp.async.wait_group 0;" ::: "memory");
        }
        __syncthreads();

        const int s = kt & 1;
        #pragma unroll
        for (int k = 0; k < 2; k++) {
            uint32_t af[4][4];
            #pragma unroll
            for (int mi = 0; mi < 4; mi++) {
                const int row = warp_m * 64 + mi * 16 + (lane & 15);
                const int col = k * 16 + (lane >> 4) * 8;
                ldsm4(af[mi][0], af[mi][1], af[mi][2], af[mi][3],
                      smem_u32(&sA[s][row * AST + col]));
            }
            uint32_t bf[NT][2];
            #pragma unroll
            for (int np = 0; np < NT / 2; np++) {
                const int n0 = warp_n * (NT * 8) + np * 16;
                const int q  = lane >> 3;
                const int row = n0 + (q & 1) * 8 + (lane & 7);
                const int col = k * 16 + (q >> 1) * 8;
                uint32_t r0, r1, r2, r3;
                ldsm4(r0, r1, r2, r3, smem_u32(&sB[s][row * AST + col]));
                bf[np*2][0] = r0; bf[np*2+1][0] = r1;
                bf[np*2][1] = r2; bf[np*2+1][1] = r3;
            }
            #pragma unroll
            for (int mi = 0; mi < 4; mi++)
                #pragma unroll
                for (int ni = 0; ni < NT; ni++)
                    mma16816(acc[mi][ni], af[mi], bf[ni]);
        }
        __syncthreads();
    }

    const int g  = lane >> 2;
    const int c2 = (lane & 3) * 2;
    #pragma unroll
    for (int mi = 0; mi < 4; mi++) {
        const int row0 = rowBase + warp_m * 64 + mi * 16 + g;
        #pragma unroll
        for (int ni = 0; ni < NT; ni++) {
            const int col = colBase + warp_n * (NT * 8) + ni * 8 + c2;
            const float b0 = bias[col], b1 = bias[col + 1];
            float v00 = acc[mi][ni][0] + b0, v01 = acc[mi][ni][1] + b1;
            float v10 = acc[mi][ni][2] + b0, v11 = acc[mi][ni][3] + b1;
            if (EPI == 1) { v00 = geluf(v00); v01 = geluf(v01); v10 = geluf(v10); v11 = geluf(v11); }
            if (OUTT == 0) {
                *(float2*)((float*)C + (size_t)row0 * N + col)       = make_float2(v00, v01);
                *(float2*)((float*)C + (size_t)(row0 + 8) * N + col) = make_float2(v10, v11);
            } else {
                __nv_bfloat16* Cb = (__nv_bfloat16*)C;
                *(__nv_bfloat162*)(Cb + (size_t)row0 * N + col)       = __float22bfloat162_rn(make_float2(v00, v01));
                *(__nv_bfloat162*)(Cb + (size_t)(row0 + 8) * N + col) = __float22bfloat162_rn(make_float2(v10, v11));
            }
        }
    }
}

// ---------------- fp32 -> bf16 converters ----------------
__global__ void cvt_bf16_kernel(const float* __restrict__ in, __nv_bfloat16* __restrict__ out, int n)
{
    int i = blockIdx.x * blockDim.x + threadIdx.x;
    if (i < n) out[i] = __float2bfloat16(in[i]);
}
__global__ void pad_xprojw_kernel(const float* __restrict__ W, __nv_bfloat16* __restrict__ out)
{
    int i = blockIdx.x * blockDim.x + threadIdx.x;      // 64*512
    int r = i >> 9, k = i & 511;
    out[i] = __float2bfloat16(r < 48 ? W[r * 512 + k] : 0.f);
}

// ---------------- SIMT SGEMM for dt_proj (K=16), writes softplus -> dtT channel-major ----
__global__ __launch_bounds__(256)
void gemm_kernel_sp(const float* __restrict__ A, int lda,
                    const float* __restrict__ W, const float* __restrict__ bias,
                    float* __restrict__ dtT, int N, int K)
{
    __shared__ float As[16][132];
    __shared__ float Bs[16][132];
    const int tid = threadIdx.x;
    const int tx = tid & 15, ty = tid >> 4;
    const int rowBase = blockIdx.y * 128, colBase = blockIdx.x * 128;
    const int r = tid >> 2, c4 = tid & 3;
    float acc[8][8];
    #pragma unroll
    for (int i = 0; i < 8; i++) {
        #pragma unroll
        for (int j = 0; j < 8; j++) acc[i][j] = 0.f;
    }
    for (int kt = 0; kt < K; kt += 16) {
        #pragma unroll
        for (int rr = r; rr < 128; rr += 64) {
            float4 va = *reinterpret_cast<const float4*>(&A[(size_t)(rowBase + rr) * lda + kt + c4 * 4]);
            As[c4*4+0][rr] = va.x; As[c4*4+1][rr] = va.y; As[c4*4+2][rr] = va.z; As[c4*4+3][rr] = va.w;
            float4 vb = *reinterpret_cast<const float4*>(&W[(size_t)(colBase + rr) * K + kt + c4 * 4]);
            Bs[c4*4+0][rr] = vb.x; Bs[c4*4+1][rr] = vb.y; Bs[c4*4+2][rr] = vb.z; Bs[c4*4+3][rr] = vb.w;
        }
        __syncthreads();
        #pragma unroll
        for (int k = 0; k < 16; k++) {
            float a8[8], b8[8];
            #pragma unroll
            for (int i = 0; i < 8; i++) a8[i] = As[k][ty * 8 + i];
            #pragma unroll
            for (int j = 0; j < 8; j++) b8[j] = Bs[k][tx * 8 + j];
            #pragma unroll
            for (int i = 0; i < 8; i++)
                #pragma unroll
                for (int j = 0; j < 8; j++) acc[i][j] = fmaf(a8[i], b8[j], acc[i][j]);
        }
        __syncthreads();
    }
    const int t0 = rowBase + ty * 8;
    const int b  = t0 >> 11;
    const int l  = t0 & 2047;
    #pragma unroll
    for (int j = 0; j < 8; j++) {
        const int col = colBase + tx * 8 + j;
        const float bj = bias[col];
        float v[8];
        #pragma unroll
        for (int i = 0; i < 8; i++) v[i] = softplusf(acc[i][j] + bj);
        float* o = dtT + ((size_t)(b * DIN + col)) * LL + l;
        *(float4*)(o)     = make_float4(v[0], v[1], v[2], v[3]);
        *(float4*)(o + 4) = make_float4(v[4], v[5], v[6], v[7]);
    }
}

// ---------------- conv+silu with transpose ----------------
__global__ __launch_bounds__(256)
void conv_silu_tr(const float* __restrict__ xz, const float* __restrict__ cw,
                  const float* __restrict__ cb, __nv_bfloat16* __restrict__ xconvb,
                  float* __restrict__ xcT, float* __restrict__ zsT)
{
    __shared__ float sxi[35][33];
    __shared__ float sout[32][33];
    __shared__ float sz[32][33];
    const int l0 = blockIdx.x * 32;
    const int d0 = blockIdx.y * 32;
    const int b  = blockIdx.z;
    const int tid = threadIdx.x;

    for (int i = tid; i < 35 * 32; i += 256) {
        const int r = i >> 5, c = i & 31;
        const int l = l0 - 3 + r;
        sxi[r][c] = (l >= 0) ? xz[((size_t)(b * LL + l)) * (2 * DIN) + d0 + c] : 0.f;
    }
    for (int i = tid; i < 32 * 32; i += 256) {
        const int r = i >> 5, c = i & 31;
        sz[r][c] = xz[((size_t)(b * LL + l0 + r)) * (2 * DIN) + DIN + d0 + c];
    }
    __syncthreads();
    for (int i = tid; i < 32 * 32; i += 256) {
        const int l = i >> 5, c = i & 31;
        const int d = d0 + c;
        float v = cb[d] + cw[d*4+3] * sxi[l+3][c] + cw[d*4+2] * sxi[l+2][c]
                        + cw[d*4+1] * sxi[l+1][c] + cw[d*4+0] * sxi[l][c];
        v = siluf(v);
        sout[l][c] = v;
        xconvb[((size_t)(b * LL + l0 + l)) * DIN + d] = __float2bfloat16(v);
    }
    __syncthreads();
    for (int i = tid; i < 32 * 32; i += 256) {
        const int c = i >> 5, l = i & 31;
        const size_t o = ((size_t)(b * DIN + d0 + c)) * LL + l0 + l;
        xcT[o] = sout[l][c];
        zsT[o] = siluf(sz[l][c]);
    }
}

// =======================================================================
// Chunked parallel scan: pass1 (chunk-local scan -> P, Hend)
// Block: 256 threads = 16 channels x 16 states, one chunk. grid=(128, GCH).
// =======================================================================
__global__ __launch_bounds__(256)
void scan_p1(const float* __restrict__ dtT, const float* __restrict__ xdbl,
             const float* __restrict__ xcT, const float* __restrict__ A_log,
             float* __restrict__ Pst, float* __restrict__ He)
{
    __shared__ __align__(16) float bufB[2][64][16];
    const int tid = threadIdx.x;
    const int cl  = tid >> 4;               // channel within block
    const int n   = tid & 15;
    const int ch  = blockIdx.x * 16 + cl;
    const int b   = ch >> 9, d = ch & (DIN - 1);
    const int chunk = blockIdx.y;
    const int l0  = chunk * CL;

    const float Aval = -expf(A_log[d * NSS + n]);
    const float* dtp = dtT + (size_t)ch * LL + l0;
    const float* xcp = xcT + (size_t)ch * LL + l0;
    const float* xrow = xdbl + ((size_t)(b * LL + l0)) * 64;

    auto fill = [&](int tile, int s) {
        // 64 steps x 16 B-floats = 256 chunks of 16B, 1 per thread
        const int r = tid >> 2, c = tid & 3;
        cp16(smem_u32(&bufB[s][r][c * 4]), xrow + ((size_t)(tile * 64 + r)) * 64 + 16 + c * 4);
    };
    fill(0, 0); CP_COMMIT();
    fill(1, 1); CP_COMMIT();

    float h = 0.f, Pp = 1.f;
    #pragma unroll
    for (int tile = 0; tile < CL / 64; tile++) {
        if (tile == 0) asm volatile("cp.async.wait_group 1;" ::: "memory");
        else           asm volatile("cp.async.wait_group 0;" ::: "memory");
        __syncthreads();
        const int s = tile & 1;
        #pragma unroll 8
        for (int j = 0; j < 64; j++) {
            const int l = tile * 64 + j;
            const float dtv = dtp[l];
            const float xv  = xcp[l];
            const float Bv  = bufB[s][j][n];
            const float dA  = __expf(dtv * Aval);
            h = fmaf(dA, h, dtv * Bv * xv);
            Pp *= dA;
        }
        __syncthreads();
    }
    const int idx = (ch * GCH + chunk) * NSS + n;
    Pst[idx] = Pp;
    He[idx]  = h;
}

// pass2: sequential combine over chunks -> Hin
__global__ __launch_bounds__(256)
void scan_p2(const float* __restrict__ Pst, const float* __restrict__ He,
             float* __restrict__ Hin)
{
    const int t  = blockIdx.x * blockDim.x + threadIdx.x;   // 0..NCH*NSS-1
    const int ch = t >> 4, n = t & 15;
    float hin = 0.f;
    #pragma unroll
    for (int c = 0; c < GCH; c++) {
        const int idx = (ch * GCH + c) * NSS + n;
        Hin[idx] = hin;
        hin = fmaf(Pst[idx], hin, He[idx]);
    }
}

// pass3: chunk scan from Hin, emit gated y. Block = 8 warps = 16 channels, one chunk.
__global__ __launch_bounds__(256)
void scan_p3(const float* __restrict__ dtT, const float* __restrict__ xdbl,
             const float* __restrict__ xcT, const float* __restrict__ zsT,
             const float* __restrict__ A_log, const float* __restrict__ D_ssm,
             const float* __restrict__ Hin, __nv_bfloat16* __restrict__ yg)
{
    __shared__ __align__(16) float buf[2][64][32];   // [stage][t_local][B(16)|C(16)]
    const int tid  = threadIdx.x;
    const int lane = tid & 31;
    const int n    = lane & 15;
    const int hw   = lane >> 4;
    const int w    = tid >> 5;
    const int ch   = blockIdx.x * 16 + w * 2 + hw;
    const int b    = ch >> 9, d = ch & (DIN - 1);
    const int chunk = blockIdx.y;
    const int l0   = chunk * CL;

    const float Aval = -expf(A_log[d * NSS + n]);
    const float Dv   = D_ssm[d];
    const float* dtp = dtT + (size_t)ch * LL + l0;
    const float* xcp = xcT + (size_t)ch * LL + l0;
    const float* zp  = zsT + (size_t)ch * LL + l0;
    const float* xrow = xdbl + ((size_t)(b * LL + l0)) * 64;

    auto fill = [&](int tile, int s) {
        #pragma unroll
        for (int i = 0; i < 2; i++) {                // 512 chunks of 16B
            const int idx = i * 256 + tid;
            const int r = idx >> 3, c = idx & 7;
            cp16(smem_u32(&buf[s][r][c * 4]), xrow + ((size_t)(tile * 64 + r)) * 64 + 16 + c * 4);
        }
    };
    fill(0, 0); CP_COMMIT();
    fill(1, 1); CP_COMMIT();

    float h = Hin[(ch * GCH + chunk) * NSS + n];
    #pragma unroll
    for (int tile = 0; tile < CL / 64; tile++) {
        if (tile == 0) asm volatile("cp.async.wait_group 1;" ::: "memory");
        else           asm volatile("cp.async.wait_group 0;" ::: "memory");
        __syncthreads();
        const int s = tile & 1;
        #pragma unroll 4
        for (int j = 0; j < 64; j++) {
            const int l = tile * 64 + j;
            const float dtv = dtp[l];
            const float xv  = xcp[l];
            const float Bv  = buf[s][j][n];
            const float Cv  = buf[s][j][16 + n];
            const float dA  = __expf(dtv * Aval);
            h = fmaf(dA, h, dtv * Bv * xv);
            float p = h * Cv;
            p += __shfl_xor_sync(0xffffffffu, p, 8);
            p += __shfl_xor_sync(0xffffffffu, p, 4);
            p += __shfl_xor_sync(0xffffffffu, p, 2);
            p += __shfl_xor_sync(0xffffffffu, p, 1);
            if (n == 0) {
                const float y = p + xv * Dv;
                yg[((size_t)(b * LL + l0 + l)) * DIN + d] = __float2bfloat16(y * zp[l]);
            }
        }
        __syncthreads();
    }
}

// ---------------- fused residual-add + LayerNorm, optional bf16 dual write ----------------
__global__ __launch_bounds__(256)
void ln_add_kernel(const float* __restrict__ a, const float* __restrict__ badd,
                   const float* __restrict__ g, const float* __restrict__ beta,
                   float* __restrict__ out, __nv_bfloat16* __restrict__ outb)
{
    const int row = blockIdx.x;
    const int tid = threadIdx.x;
    const float v = a[(size_t)row * DD + tid] + badd[(size_t)row * DD + tid];
    float s = v, s2 = v * v;
    #pragma unroll
    for (int m = 16; m > 0; m >>= 1) {
        s  += __shfl_xor_sync(0xffffffffu, s,  m);
        s2 += __shfl_xor_sync(0xffffffffu, s2, m);
    }
    __shared__ float sh[8], sh2[8];
    if ((tid & 31) == 0) { sh[tid >> 5] = s; sh2[tid >> 5] = s2; }
    __syncthreads();
    float ts = 0.f, ts2 = 0.f;
    #pragma unroll
    for (int i = 0; i < 8; i++) { ts += sh[i]; ts2 += sh2[i]; }
    const float mean = ts * (1.f / DD);
    const float var  = ts2 * (1.f / DD) - mean * mean;
    const float inv  = rsqrtf(var + 1e-5f);
    const float o = (v - mean) * inv * g[tid] + beta[tid];
    out[(size_t)row * DD + tid] = o;
    if (outb) outb[(size_t)row * DD + tid] = __float2bfloat16(o);
}

// ---------------- launch ----------------
extern "C" void kernel_launch(void* const* d_in, const int* in_sizes, int n_in,
                              void* d_out, int out_size)
{
    const float* x          = (const float*)d_in[0];
    const float* in_proj_w  = (const float*)d_in[1];
    const float* in_proj_b  = (const float*)d_in[2];
    const float* conv_w     = (const float*)d_in[3];
    const float* conv_b     = (const float*)d_in[4];
    const float* x_proj_w   = (const float*)d_in[5];
    const float* dt_proj_w  = (const float*)d_in[6];
    const float* dt_proj_b  = (const float*)d_in[7];
    const float* A_log      = (const float*)d_in[8];
    const float* D_ssm      = (const float*)d_in[9];
    const float* out_proj_w = (const float*)d_in[10];
    const float* out_proj_b = (const float*)d_in[11];
    const float* ln1_g      = (const float*)d_in[12];
    const float* ln1_b      = (const float*)d_in[13];
    const float* fc1_w      = (const float*)d_in[14];
    const float* fc1_b      = (const float*)d_in[15];
    const float* fc2_w      = (const float*)d_in[16];
    const float* fc2_b      = (const float*)d_in[17];
    const float* ln2_g      = (const float*)d_in[18];
    const float* ln2_b      = (const float*)d_in[19];
    float* out = (float*)d_out;

    float *xz, *xcT, *zsT, *xdbl, *dtT, *Pst, *He, *Hin, *ssm, *y1, *f2, *zero;
    __nv_bfloat16 *xconvb, *ygb, *y1b, *h1b, *xb, *w_in, *w_xp, *w_out, *w_fc1, *w_fc2;
    cudaGetSymbolAddress((void**)&xz,     g_xz);
    cudaGetSymbolAddress((void**)&xcT,    g_xcT);
    cudaGetSymbolAddress((void**)&zsT,    g_zsT);
    cudaGetSymbolAddress((void**)&xconvb, g_xconvb);
    cudaGetSymbolAddress((void**)&xdbl,   g_xdbl);
    cudaGetSymbolAddress((void**)&dtT,    g_dtT);
    cudaGetSymbolAddress((void**)&Pst,    g_P);
    cudaGetSymbolAddress((void**)&He,     g_He);
    cudaGetSymbolAddress((void**)&Hin,    g_Hin);
    cudaGetSymbolAddress((void**)&ygb,    g_ygb);
    cudaGetSymbolAddress((void**)&ssm,    g_ssm);
    cudaGetSymbolAddress((void**)&y1,     g_y1);
    cudaGetSymbolAddress((void**)&y1b,    g_y1b);
    cudaGetSymbolAddress((void**)&h1b,    g_h1b);
    cudaGetSymbolAddress((void**)&f2,     g_f2);
    cudaGetSymbolAddress((void**)&xb,     g_xb);
    cudaGetSymbolAddress((void**)&w_in,   g_w_in);
    cudaGetSymbolAddress((void**)&w_xp,   g_w_xp);
    cudaGetSymbolAddress((void**)&w_out,  g_w_out);
    cudaGetSymbolAddress((void**)&w_fc1,  g_w_fc1);
    cudaGetSymbolAddress((void**)&w_fc2,  g_w_fc2);
    cudaGetSymbolAddress((void**)&zero,   g_zero);

    // 1-3) conversions (slots 1-3 so the in_proj GEMM lands in profiled slot 4)
    cvt_bf16_kernel<<<(TOK*DD+255)/256, 256>>>(x, xb, TOK*DD);
    cvt_bf16_kernel<<<(2*DIN*DD+255)/256, 256>>>(in_proj_w, w_in, 2*DIN*DD);
    pad_xprojw_kernel<<<(64*DIN+255)/256, 256>>>(x_proj_w, w_xp);
    // 4) in_proj GEMM -> xz fp32   [PROFILED]
    mma_gemm<128,0,0><<<dim3(2*DIN/128, TOK/128), 256>>>(xb, w_in, in_proj_b, xz, 2*DIN, DD);
    // 5) conv + silu + transpose
    conv_silu_tr<<<dim3(LL/32, DIN/32, BB), 256>>>(xz, conv_w, conv_b, xconvb, xcT, zsT);
    // 6) x_proj GEMM -> xdbl
    mma_gemm<64,0,0><<<dim3(1, TOK/128), 256>>>(xconvb, w_xp, zero, xdbl, 64, DIN);
    // 7) dt_proj + softplus -> dtT channel-major
    gemm_kernel_sp<<<dim3(DIN/128, TOK/128), 256>>>(xdbl, 64, dt_proj_w, dt_proj_b, dtT, DIN, DTR_);
    // 8-10) chunked parallel scan
    scan_p1<<<dim3(NCH/16, GCH), 256>>>(dtT, xdbl, xcT, A_log, Pst, He);
    scan_p2<<<(NCH*NSS)/256, 256>>>(Pst, He, Hin);
    scan_p3<<<dim3(NCH/16, GCH), 256>>>(dtT, xdbl, xcT, zsT, A_log, D_ssm, Hin, ygb);
    // 11) out_proj weight conversion
    cvt_bf16_kernel<<<(DD*DIN+255)/256, 256>>>(out_proj_w, w_out, DD*DIN);
    // 12) out_proj GEMM -> ssm
    mma_gemm<128,0,0><<<dim3(DD/128, TOK/128), 256>>>(ygb, w_out, out_proj_b, ssm, DD, DIN);
    // 13) LN1(x + ssm)
    ln_add_kernel<<<TOK, 256>>>(x, ssm, ln1_g, ln1_b, y1, y1b);
    // 14,15) fc1 + gelu
    cvt_bf16_kernel<<<(DFF_*DD+255)/256, 256>>>(fc1_w, w_fc1, DFF_*DD);
    mma_gemm<128,1,1><<<dim3(DFF_/128, TOK/128), 256>>>(y1b, w_fc1, fc1_b, h1b, DFF_, DD);
    // 16,17) fc2 + gelu
    cvt_bf16_kernel<<<(DD*DFF_+255)/256, 256>>>(fc2_w, w_fc2, DD*DFF_);
    mma_gemm<128,1,0><<<dim3(DD/128, TOK/128), 256>>>(h1b, w_fc2, fc2_b, f2, DD, DFF_);
    // 18) LN2(y1 + ffn) -> out
    ln_add_kernel<<<TOK, 256>>>(y1, f2, ln2_g, ln2_b, out, (__nv_bfloat16*)0);
}

// round 7
// speedup vs baseline: 7.1381x; 1.0223x over previous
#include <cuda_runtime.h>
#include <cuda_bf16.h>
#include <math.h>
#include <stdint.h>

// Problem constants (fixed shapes)
#define BB   4
#define LL   2048
#define DD   256
#define DIN  512
#define NSS  16
#define DTR_ 16
#define DFF_ 1024
#define TOK  (BB*LL)      // 8192
#define NCH  (BB*DIN)     // 2048 scan channels
#define GCH  16           // scan chunks
#define CL   (LL/GCH)     // 128 steps per chunk

// ---------------- scratch (static device memory) ----------------
__device__ float          g_xz    [TOK * 2 * DIN];
__device__ float          g_xcT   [TOK * DIN];
__device__ float          g_zsT   [TOK * DIN];
__device__ __nv_bfloat16  g_xconvb[TOK * DIN];
__device__ float          g_xdbl  [TOK * 64];
__device__ float          g_dtT   [TOK * DIN];
__device__ float          g_P     [NCH * GCH * NSS];
__device__ float          g_He    [NCH * GCH * NSS];
__device__ float          g_Hin   [NCH * GCH * NSS];
__device__ __nv_bfloat16  g_ygb   [TOK * DIN];
__device__ float          g_ssm   [TOK * DD];
__device__ float          g_y1    [TOK * DD];
__device__ __nv_bfloat16  g_y1b   [TOK * DD];
__device__ __nv_bfloat16  g_h1b   [TOK * DFF_];
__device__ float          g_f2    [TOK * DD];
__device__ __nv_bfloat16  g_xb    [TOK * DD];
__device__ __nv_bfloat16  g_w_in  [2 * DIN * DD];
__device__ __nv_bfloat16  g_w_xp  [64 * DIN];
__device__ __nv_bfloat16  g_w_out [DD * DIN];
__device__ __nv_bfloat16  g_w_fc1 [DFF_ * DD];
__device__ __nv_bfloat16  g_w_fc2 [DD * DFF_];
__device__ float          g_zero  [64];

// ---------------- math helpers ----------------
__device__ __forceinline__ float siluf(float v)     { return v / (1.f + __expf(-v)); }
__device__ __forceinline__ float geluf(float v)     { return 0.5f * v * (1.f + erff(v * 0.70710678118654752f)); }
__device__ __forceinline__ float softplusf(float v) { return fmaxf(v, 0.f) + log1pf(__expf(-fabsf(v))); }

__device__ __forceinline__ uint32_t smem_u32(const void* p) {
    uint32_t a;
    asm("{ .reg .u64 t; cvta.to.shared.u64 t, %1; cvt.u32.u64 %0, t; }" : "=r"(a) : "l"(p));
    return a;
}
__device__ __forceinline__ void ldsm4(uint32_t& r0, uint32_t& r1, uint32_t& r2, uint32_t& r3, uint32_t addr) {
    asm volatile("ldmatrix.sync.aligned.m8n8.x4.shared.b16 {%0,%1,%2,%3}, [%4];"
                 : "=r"(r0), "=r"(r1), "=r"(r2), "=r"(r3) : "r"(addr));
}
__device__ __forceinline__ void mma16816(float* c, const uint32_t* a, const uint32_t* b) {
    asm volatile("mma.sync.aligned.m16n8k16.row.col.f32.bf16.bf16.f32 "
                 "{%0,%1,%2,%3},{%4,%5,%6,%7},{%8,%9},{%0,%1,%2,%3};"
                 : "+f"(c[0]), "+f"(c[1]), "+f"(c[2]), "+f"(c[3])
                 : "r"(a[0]), "r"(a[1]), "r"(a[2]), "r"(a[3]), "r"(b[0]), "r"(b[1]));
}
__device__ __forceinline__ void cp16(uint32_t dst, const void* src) {
    asm volatile("cp.async.cg.shared.global [%0], [%1], 16;" :: "r"(dst), "l"(src));
}
#define CP_COMMIT() asm volatile("cp.async.commit_group;" ::: "memory")

// =======================================================================
// SM80-style bf16 GEMM, 3-stage cp.async pipeline, dynamic smem.
// BM=128, BN template (128/64), BK=32, 256 threads = 2(M) x 4(N) warps.
// EPI: 0 none, 1 gelu.  OUTT: 0 fp32, 1 bf16.
// =======================================================================
template<int BN, int EPI, int OUTT>
__global__ __launch_bounds__(256)
void mma_gemm(const __nv_bfloat16* __restrict__ A, const __nv_bfloat16* __restrict__ W,
              const float* __restrict__ bias, void* __restrict__ C, int N, int K)
{
    constexpr int BM  = 128;
    constexpr int BK  = 32;
    constexpr int AST = 40;
    constexpr int NT  = BN / 32;
    constexpr int ASZ = BM * AST;       // elems per A stage
    constexpr int BSZ = BN * AST;       // elems per B stage

    extern __shared__ __nv_bfloat16 smem[];
    __nv_bfloat16* sA = smem;                 // 3 stages
    __nv_bfloat16* sB = smem + 3 * ASZ;       // 3 stages

    const int tid  = threadIdx.x;
    const int wid  = tid >> 5;
    const int lane = tid & 31;
    const int warp_m = wid & 1;
    const int warp_n = wid >> 1;
    const int rowBase = blockIdx.y * BM;
    const int colBase = blockIdx.x * BN;
    const int NK = K >> 5;

    auto prefetch = [&](int s, int kc) {
        __nv_bfloat16* As = sA + s * ASZ;
        __nv_bfloat16* Bs = sB + s * BSZ;
        #pragma unroll
        for (int i = 0; i < 2; i++) {
            const int cidx = i * 256 + tid;
            const int row = cidx >> 2, c4 = cidx & 3;
            cp16(smem_u32(&As[row * AST + c4 * 8]),
                 A + (size_t)(rowBase + row) * K + kc * BK + c4 * 8);
        }
        #pragma unroll
        for (int i = 0; i < BN / 64; i++) {
            const int cidx = i * 256 + tid;
            const int row = cidx >> 2, c4 = cidx & 3;
            cp16(smem_u32(&Bs[row * AST + c4 * 8]),
                 W + (size_t)(colBase + row) * K + kc * BK + c4 * 8);
        }
    };

    float acc[4][NT][4];
    #pragma unroll
    for (int mi = 0; mi < 4; mi++)
        #pragma unroll
        for (int ni = 0; ni < NT; ni++)
            #pragma unroll
            for (int r = 0; r < 4; r++) acc[mi][ni][r] = 0.f;

    prefetch(0, 0); CP_COMMIT();
    if (NK > 1) { prefetch(1, 1); CP_COMMIT(); }

    for (int kt = 0; kt < NK; kt++) {
        // issue prefetch 2 ahead (stage being overwritten was consumed at kt-1,
        // behind the trailing __syncthreads of that iteration)
        if (kt + 2 < NK) { prefetch((kt + 2) % 3, kt + 2); CP_COMMIT(); }
        // wait until group kt complete
        if (kt + 2 < NK)      asm volatile("cp.async.wait_group 2;" ::: "memory");
        else if (kt + 1 < NK) asm volatile("cp.async.wait_group 1;" ::: "memory");
        else                  asm volatile("cp.async.wait_group 0;" ::: "memory");
        __syncthreads();

        const int s = kt % 3;
        __nv_bfloat16* As = sA + s * ASZ;
        __nv_bfloat16* Bs = sB + s * BSZ;
        #pragma unroll
        for (int k = 0; k < 2; k++) {
            uint32_t af[4][4];
            #pragma unroll
            for (int mi = 0; mi < 4; mi++) {
                const int row = warp_m * 64 + mi * 16 + (lane & 15);
                const int col = k * 16 + (lane >> 4) * 8;
                ldsm4(af[mi][0], af[mi][1], af[mi][2], af[mi][3],
                      smem_u32(&As[row * AST + col]));
            }
            uint32_t bf[NT][2];
            #pragma unroll
            for (int np = 0; np < NT / 2; np++) {
                const int n0 = warp_n * (NT * 8) + np * 16;
                const int q  = lane >> 3;
                const int row = n0 + (q & 1) * 8 + (lane & 7);
                const int col = k * 16 + (q >> 1) * 8;
                uint32_t r0, r1, r2, r3;
                ldsm4(r0, r1, r2, r3, smem_u32(&Bs[row * AST + col]));
                bf[np*2][0] = r0; bf[np*2+1][0] = r1;
                bf[np*2][1] = r2; bf[np*2+1][1] = r3;
            }
            #pragma unroll
            for (int mi = 0; mi < 4; mi++)
                #pragma unroll
                for (int ni = 0; ni < NT; ni++)
                    mma16816(acc[mi][ni], af[mi], bf[ni]);
        }
        __syncthreads();
    }

    const int g  = lane >> 2;
    const int c2 = (lane & 3) * 2;
    #pragma unroll
    for (int mi = 0; mi < 4; mi++) {
        const int row0 = rowBase + warp_m * 64 + mi * 16 + g;
        #pragma unroll
        for (int ni = 0; ni < NT; ni++) {
            const int col = colBase + warp_n * (NT * 8) + ni * 8 + c2;
            const float b0 = bias[col], b1 = bias[col + 1];
            float v00 = acc[mi][ni][0] + b0, v01 = acc[mi][ni][1] + b1;
            float v10 = acc[mi][ni][2] + b0, v11 = acc[mi][ni][3] + b1;
            if (EPI == 1) { v00 = geluf(v00); v01 = geluf(v01); v10 = geluf(v10); v11 = geluf(v11); }
            if (OUTT == 0) {
                *(float2*)((float*)C + (size_t)row0 * N + col)       = make_float2(v00, v01);
                *(float2*)((float*)C + (size_t)(row0 + 8) * N + col) = make_float2(v10, v11);
            } else {
                __nv_bfloat16* Cb = (__nv_bfloat16*)C;
                *(__nv_bfloat162*)(Cb + (size_t)row0 * N + col)       = __float22bfloat162_rn(make_float2(v00, v01));
                *(__nv_bfloat162*)(Cb + (size_t)(row0 + 8) * N + col) = __float22bfloat162_rn(make_float2(v10, v11));
            }
        }
    }
}

// ---------------- converters ----------------
__global__ void cvt_bf16_kernel(const float* __restrict__ in, __nv_bfloat16* __restrict__ out, int n)
{
    int i = blockIdx.x * blockDim.x + threadIdx.x;
    if (i < n) out[i] = __float2bfloat16(in[i]);
}
// all four big weight matrices in one launch
__global__ void cvt_weights_kernel(const float* __restrict__ a, __nv_bfloat16* __restrict__ oa,
                                   const float* __restrict__ b, __nv_bfloat16* __restrict__ ob,
                                   const float* __restrict__ c, __nv_bfloat16* __restrict__ oc,
                                   const float* __restrict__ d, __nv_bfloat16* __restrict__ od)
{
    int i = blockIdx.x * blockDim.x + threadIdx.x;
    if (i < 2*DIN*DD)            { oa[i] = __float2bfloat16(a[i]); return; }
    i -= 2*DIN*DD;
    if (i < DD*DIN)              { ob[i] = __float2bfloat16(b[i]); return; }
    i -= DD*DIN;
    if (i < DFF_*DD)             { oc[i] = __float2bfloat16(c[i]); return; }
    i -= DFF_*DD;
    if (i < DD*DFF_)             { od[i] = __float2bfloat16(d[i]); }
}
__global__ void pad_xprojw_kernel(const float* __restrict__ W, __nv_bfloat16* __restrict__ out)
{
    int i = blockIdx.x * blockDim.x + threadIdx.x;
    int r = i >> 9, k = i & 511;
    out[i] = __float2bfloat16(r < 48 ? W[r * 512 + k] : 0.f);
}

// ---------------- SIMT SGEMM for dt_proj (K=16) -> dtT channel-major ----------------
__global__ __launch_bounds__(256)
void gemm_kernel_sp(const float* __restrict__ A, int lda,
                    const float* __restrict__ W, const float* __restrict__ bias,
                    float* __restrict__ dtT, int N, int K)
{
    __shared__ float As[16][132];
    __shared__ float Bs[16][132];
    const int tid = threadIdx.x;
    const int tx = tid & 15, ty = tid >> 4;
    const int rowBase = blockIdx.y * 128, colBase = blockIdx.x * 128;
    const int r = tid >> 2, c4 = tid & 3;
    float acc[8][8];
    #pragma unroll
    for (int i = 0; i < 8; i++) {
        #pragma unroll
        for (int j = 0; j < 8; j++) acc[i][j] = 0.f;
    }
    for (int kt = 0; kt < K; kt += 16) {
        #pragma unroll
        for (int rr = r; rr < 128; rr += 64) {
            float4 va = *reinterpret_cast<const float4*>(&A[(size_t)(rowBase + rr) * lda + kt + c4 * 4]);
            As[c4*4+0][rr] = va.x; As[c4*4+1][rr] = va.y; As[c4*4+2][rr] = va.z; As[c4*4+3][rr] = va.w;
            float4 vb = *reinterpret_cast<const float4*>(&W[(size_t)(colBase + rr) * K + kt + c4 * 4]);
            Bs[c4*4+0][rr] = vb.x; Bs[c4*4+1][rr] = vb.y; Bs[c4*4+2][rr] = vb.z; Bs[c4*4+3][rr] = vb.w;
        }
        __syncthreads();
        #pragma unroll
        for (int k = 0; k < 16; k++) {
            float a8[8], b8[8];
            #pragma unroll
            for (int i = 0; i < 8; i++) a8[i] = As[k][ty * 8 + i];
            #pragma unroll
            for (int j = 0; j < 8; j++) b8[j] = Bs[k][tx * 8 + j];
            #pragma unroll
            for (int i = 0; i < 8; i++)
                #pragma unroll
                for (int j = 0; j < 8; j++) acc[i][j] = fmaf(a8[i], b8[j], acc[i][j]);
        }
        __syncthreads();
    }
    const int t0 = rowBase + ty * 8;
    const int b  = t0 >> 11;
    const int l  = t0 & 2047;
    #pragma unroll
    for (int j = 0; j < 8; j++) {
        const int col = colBase + tx * 8 + j;
        const float bj = bias[col];
        float v[8];
        #pragma unroll
        for (int i = 0; i < 8; i++) v[i] = softplusf(acc[i][j] + bj);
        float* o = dtT + ((size_t)(b * DIN + col)) * LL + l;
        *(float4*)(o)     = make_float4(v[0], v[1], v[2], v[3]);
        *(float4*)(o + 4) = make_float4(v[4], v[5], v[6], v[7]);
    }
}

// ---------------- conv+silu with transpose ----------------
__global__ __launch_bounds__(256)
void conv_silu_tr(const float* __restrict__ xz, const float* __restrict__ cw,
                  const float* __restrict__ cb, __nv_bfloat16* __restrict__ xconvb,
                  float* __restrict__ xcT, float* __restrict__ zsT)
{
    __shared__ float sxi[35][33];
    __shared__ float sout[32][33];
    __shared__ float sz[32][33];
    const int l0 = blockIdx.x * 32;
    const int d0 = blockIdx.y * 32;
    const int b  = blockIdx.z;
    const int tid = threadIdx.x;

    for (int i = tid; i < 35 * 32; i += 256) {
        const int r = i >> 5, c = i & 31;
        const int l = l0 - 3 + r;
        sxi[r][c] = (l >= 0) ? xz[((size_t)(b * LL + l)) * (2 * DIN) + d0 + c] : 0.f;
    }
    for (int i = tid; i < 32 * 32; i += 256) {
        const int r = i >> 5, c = i & 31;
        sz[r][c] = xz[((size_t)(b * LL + l0 + r)) * (2 * DIN) + DIN + d0 + c];
    }
    __syncthreads();
    for (int i = tid; i < 32 * 32; i += 256) {
        const int l = i >> 5, c = i & 31;
        const int d = d0 + c;
        float v = cb[d] + cw[d*4+3] * sxi[l+3][c] + cw[d*4+2] * sxi[l+2][c]
                        + cw[d*4+1] * sxi[l+1][c] + cw[d*4+0] * sxi[l][c];
        v = siluf(v);
        sout[l][c] = v;
        xconvb[((size_t)(b * LL + l0 + l)) * DIN + d] = __float2bfloat16(v);
    }
    __syncthreads();
    for (int i = tid; i < 32 * 32; i += 256) {
        const int c = i >> 5, l = i & 31;
        const size_t o = ((size_t)(b * DIN + d0 + c)) * LL + l0 + l;
        xcT[o] = sout[l][c];
        zsT[o] = siluf(sz[l][c]);
    }
}

// ---------------- chunked parallel scan ----------------
__global__ __launch_bounds__(256)
void scan_p1(const float* __restrict__ dtT, const float* __restrict__ xdbl,
             const float* __restrict__ xcT, const float* __restrict__ A_log,
             float* __restrict__ Pst, float* __restrict__ He)
{
    __shared__ __align__(16) float bufB[2][64][16];
    const int tid = threadIdx.x;
    const int cl  = tid >> 4;
    const int n   = tid & 15;
    const int ch  = blockIdx.x * 16 + cl;
    const int b   = ch >> 9, d = ch & (DIN - 1);
    const int chunk = blockIdx.y;
    const int l0  = chunk * CL;

    const float Aval = -expf(A_log[d * NSS + n]);
    const float* dtp = dtT + (size_t)ch * LL + l0;
    const float* xcp = xcT + (size_t)ch * LL + l0;
    const float* xrow = xdbl + ((size_t)(b * LL + l0)) * 64;

    auto fill = [&](int tile, int s) {
        const int r = tid >> 2, c = tid & 3;
        cp16(smem_u32(&bufB[s][r][c * 4]), xrow + ((size_t)(tile * 64 + r)) * 64 + 16 + c * 4);
    };
    fill(0, 0); CP_COMMIT();
    fill(1, 1); CP_COMMIT();

    float h = 0.f, Pp = 1.f;
    #pragma unroll
    for (int tile = 0; tile < CL / 64; tile++) {
        if (tile == 0) asm volatile("cp.async.wait_group 1;" ::: "memory");
        else           asm volatile("cp.async.wait_group 0;" ::: "memory");
        __syncthreads();
        const int s = tile & 1;
        #pragma unroll 8
        for (int j = 0; j < 64; j++) {
            const int l = tile * 64 + j;
            const float dtv = dtp[l];
            const float xv  = xcp[l];
            const float Bv  = bufB[s][j][n];
            const float dA  = __expf(dtv * Aval);
            h = fmaf(dA, h, dtv * Bv * xv);
            Pp *= dA;
        }
        __syncthreads();
    }
    const int idx = (ch * GCH + chunk) * NSS + n;
    Pst[idx] = Pp;
    He[idx]  = h;
}

__global__ __launch_bounds__(256)
void scan_p2(const float* __restrict__ Pst, const float* __restrict__ He,
             float* __restrict__ Hin)
{
    const int t  = blockIdx.x * blockDim.x + threadIdx.x;
    const int ch = t >> 4, n = t & 15;
    float hin = 0.f;
    #pragma unroll
    for (int c = 0; c < GCH; c++) {
        const int idx = (ch * GCH + c) * NSS + n;
        Hin[idx] = hin;
        hin = fmaf(Pst[idx], hin, He[idx]);
    }
}

__global__ __launch_bounds__(256)
void scan_p3(const float* __restrict__ dtT, const float* __restrict__ xdbl,
             const float* __restrict__ xcT, const float* __restrict__ zsT,
             const float* __restrict__ A_log, const float* __restrict__ D_ssm,
             const float* __restrict__ Hin, __nv_bfloat16* __restrict__ yg)
{
    __shared__ __align__(16) float buf[2][64][32];
    const int tid  = threadIdx.x;
    const int lane = tid & 31;
    const int n    = lane & 15;
    const int hw   = lane >> 4;
    const int w    = tid >> 5;
    const int ch   = blockIdx.x * 16 + w * 2 + hw;
    const int b    = ch >> 9, d = ch & (DIN - 1);
    const int chunk = blockIdx.y;
    const int l0   = chunk * CL;

    const float Aval = -expf(A_log[d * NSS + n]);
    const float Dv   = D_ssm[d];
    const float* dtp = dtT + (size_t)ch * LL + l0;
    const float* xcp = xcT + (size_t)ch * LL + l0;
    const float* zp  = zsT + (size_t)ch * LL + l0;
    const float* xrow = xdbl + ((size_t)(b * LL + l0)) * 64;

    auto fill = [&](int tile, int s) {
        #pragma unroll
        for (int i = 0; i < 2; i++) {
            const int idx = i * 256 + tid;
            const int r = idx >> 3, c = idx & 7;
            cp16(smem_u32(&buf[s][r][c * 4]), xrow + ((size_t)(tile * 64 + r)) * 64 + 16 + c * 4);
        }
    };
    fill(0, 0); CP_COMMIT();
    fill(1, 1); CP_COMMIT();

    float h = Hin[(ch * GCH + chunk) * NSS + n];
    #pragma unroll
    for (int tile = 0; tile < CL / 64; tile++) {
        if (tile == 0) asm volatile("cp.async.wait_group 1;" ::: "memory");
        else           asm volatile("cp.async.wait_group 0;" ::: "memory");
        __syncthreads();
        const int s = tile & 1;
        #pragma unroll 4
        for (int j = 0; j < 64; j++) {
            const int l = tile * 64 + j;
            const float dtv = dtp[l];
            const float xv  = xcp[l];
            const float Bv  = buf[s][j][n];
            const float Cv  = buf[s][j][16 + n];
            const float dA  = __expf(dtv * Aval);
            h = fmaf(dA, h, dtv * Bv * xv);
            float p = h * Cv;
            p += __shfl_xor_sync(0xffffffffu, p, 8);
            p += __shfl_xor_sync(0xffffffffu, p, 4);
            p += __shfl_xor_sync(0xffffffffu, p, 2);
            p += __shfl_xor_sync(0xffffffffu, p, 1);
            if (n == 0) {
                const float y = p + xv * Dv;
                yg[((size_t)(b * LL + l0 + l)) * DIN + d] = __float2bfloat16(y * zp[l]);
            }
        }
        __syncthreads();
    }
}

// ---------------- fused residual-add + LayerNorm ----------------
__global__ __launch_bounds__(256)
void ln_add_kernel(const float* __restrict__ a, const float* __restrict__ badd,
                   const float* __restrict__ g, const float* __restrict__ beta,
                   float* __restrict__ out, __nv_bfloat16* __restrict__ outb)
{
    const int row = blockIdx.x;
    const int tid = threadIdx.x;
    const float v = a[(size_t)row * DD + tid] + badd[(size_t)row * DD + tid];
    float s = v, s2 = v * v;
    #pragma unroll
    for (int m = 16; m > 0; m >>= 1) {
        s  += __shfl_xor_sync(0xffffffffu, s,  m);
        s2 += __shfl_xor_sync(0xffffffffu, s2, m);
    }
    __shared__ float sh[8], sh2[8];
    if ((tid & 31) == 0) { sh[tid >> 5] = s; sh2[tid >> 5] = s2; }
    __syncthreads();
    float ts = 0.f, ts2 = 0.f;
    #pragma unroll
    for (int i = 0; i < 8; i++) { ts += sh[i]; ts2 += sh2[i]; }
    const float mean = ts * (1.f / DD);
    const float var  = ts2 * (1.f / DD) - mean * mean;
    const float inv  = rsqrtf(var + 1e-5f);
    const float o = (v - mean) * inv * g[tid] + beta[tid];
    out[(size_t)row * DD + tid] = o;
    if (outb) outb[(size_t)row * DD + tid] = __float2bfloat16(o);
}

// ---------------- launch ----------------
extern "C" void kernel_launch(void* const* d_in, const int* in_sizes, int n_in,
                              void* d_out, int out_size)
{
    const float* x          = (const float*)d_in[0];
    const float* in_proj_w  = (const float*)d_in[1];
    const float* in_proj_b  = (const float*)d_in[2];
    const float* conv_w     = (const float*)d_in[3];
    const float* conv_b     = (const float*)d_in[4];
    const float* x_proj_w   = (const float*)d_in[5];
    const float* dt_proj_w  = (const float*)d_in[6];
    const float* dt_proj_b  = (const float*)d_in[7];
    const float* A_log      = (const float*)d_in[8];
    const float* D_ssm      = (const float*)d_in[9];
    const float* out_proj_w = (const float*)d_in[10];
    const float* out_proj_b = (const float*)d_in[11];
    const float* ln1_g      = (const float*)d_in[12];
    const float* ln1_b      = (const float*)d_in[13];
    const float* fc1_w      = (const float*)d_in[14];
    const float* fc1_b      = (const float*)d_in[15];
    const float* fc2_w      = (const float*)d_in[16];
    const float* fc2_b      = (const float*)d_in[17];
    const float* ln2_g      = (const float*)d_in[18];
    const float* ln2_b      = (const float*)d_in[19];
    float* out = (float*)d_out;

    float *xz, *xcT, *zsT, *xdbl, *dtT, *Pst, *He, *Hin, *ssm, *y1, *f2, *zero;
    __nv_bfloat16 *xconvb, *ygb, *y1b, *h1b, *xb, *w_in, *w_xp, *w_out, *w_fc1, *w_fc2;
    cudaGetSymbolAddress((void**)&xz,     g_xz);
    cudaGetSymbolAddress((void**)&xcT,    g_xcT);
    cudaGetSymbolAddress((void**)&zsT,    g_zsT);
    cudaGetSymbolAddress((void**)&xconvb, g_xconvb);
    cudaGetSymbolAddress((void**)&xdbl,   g_xdbl);
    cudaGetSymbolAddress((void**)&dtT,    g_dtT);
    cudaGetSymbolAddress((void**)&Pst,    g_P);
    cudaGetSymbolAddress((void**)&He,     g_He);
    cudaGetSymbolAddress((void**)&Hin,    g_Hin);
    cudaGetSymbolAddress((void**)&ygb,    g_ygb);
    cudaGetSymbolAddress((void**)&ssm,    g_ssm);
    cudaGetSymbolAddress((void**)&y1,     g_y1);
    cudaGetSymbolAddress((void**)&y1b,    g_y1b);
    cudaGetSymbolAddress((void**)&h1b,    g_h1b);
    cudaGetSymbolAddress((void**)&f2,     g_f2);
    cudaGetSymbolAddress((void**)&xb,     g_xb);
    cudaGetSymbolAddress((void**)&w_in,   g_w_in);
    cudaGetSymbolAddress((void**)&w_xp,   g_w_xp);
    cudaGetSymbolAddress((void**)&w_out,  g_w_out);
    cudaGetSymbolAddress((void**)&w_fc1,  g_w_fc1);
    cudaGetSymbolAddress((void**)&w_fc2,  g_w_fc2);
    cudaGetSymbolAddress((void**)&zero,   g_zero);

    // dynamic smem sizes: 3 stages of (BM + BN) * AST bf16
    const int SM128 = 3 * (128 + 128) * 40 * 2;  // 61440
    const int SM64  = 3 * (128 + 64)  * 40 * 2;  // 46080
    cudaFuncSetAttribute(mma_gemm<128,0,0>, cudaFuncAttributeMaxDynamicSharedMemorySize, SM128);
    cudaFuncSetAttribute(mma_gemm<128,1,1>, cudaFuncAttributeMaxDynamicSharedMemorySize, SM128);
    cudaFuncSetAttribute(mma_gemm<128,1,0>, cudaFuncAttributeMaxDynamicSharedMemorySize, SM128);
    cudaFuncSetAttribute(mma_gemm<64,0,0>,  cudaFuncAttributeMaxDynamicSharedMemorySize, SM64);

    // 1-3) conversions (in_proj GEMM stays in launch slot 4 for profiling)
    cvt_bf16_kernel<<<(TOK*DD+255)/256, 256>>>(x, xb, TOK*DD);
    cvt_weights_kernel<<<((2*DIN*DD + DD*DIN + DFF_*DD + DD*DFF_) + 255)/256, 256>>>(
        in_proj_w, w_in, out_proj_w, w_out, fc1_w, w_fc1, fc2_w, w_fc2);
    pad_xprojw_kernel<<<(64*DIN+255)/256, 256>>>(x_proj_w, w_xp);
    // 4) in_proj GEMM -> xz fp32   [PROFILED]
    mma_gemm<128,0,0><<<dim3(2*DIN/128, TOK/128), 256, SM128>>>(xb, w_in, in_proj_b, xz, 2*DIN, DD);
    // 5) conv + silu + transpose
    conv_silu_tr<<<dim3(LL/32, DIN/32, BB), 256>>>(xz, conv_w, conv_b, xconvb, xcT, zsT);
    // 6) x_proj GEMM -> xdbl
    mma_gemm<64,0,0><<<dim3(1, TOK/128), 256, SM64>>>(xconvb, w_xp, zero, xdbl, 64, DIN);
    // 7) dt_proj + softplus -> dtT channel-major
    gemm_kernel_sp<<<dim3(DIN/128, TOK/128), 256>>>(xdbl, 64, dt_proj_w, dt_proj_b, dtT, DIN, DTR_);
    // 8-10) chunked parallel scan
    scan_p1<<<dim3(NCH/16, GCH), 256>>>(dtT, xdbl, xcT, A_log, Pst, He);
    scan_p2<<<(NCH*NSS)/256, 256>>>(Pst, He, Hin);
    scan_p3<<<dim3(NCH/16, GCH), 256>>>(dtT, xdbl, xcT, zsT, A_log, D_ssm, Hin, ygb);
    // 11) out_proj GEMM -> ssm
    mma_gemm<128,0,0><<<dim3(DD/128, TOK/128), 256, SM128>>>(ygb, w_out, out_proj_b, ssm, DD, DIN);
    // 12) LN1(x + ssm)
    ln_add_kernel<<<TOK, 256>>>(x, ssm, ln1_g, ln1_b, y1, y1b);
    // 13) fc1 + gelu
    mma_gemm<128,1,1><<<dim3(DFF_/128, TOK/128), 256, SM128>>>(y1b, w_fc1, fc1_b, h1b, DFF_, DD);
    // 14) fc2 + gelu
    mma_gemm<128,1,0><<<dim3(DD/128, TOK/128), 256, SM128>>>(h1b, w_fc2, fc2_b, f2, DD, DFF_);
    // 15) LN2(y1 + ffn) -> out
    ln_add_kernel<<<TOK, 256>>>(y1, f2, ln2_g, ln2_b, out, (__nv_bfloat16*)0);
}

// round 8
// speedup vs baseline: 7.4231x; 1.0399x over previous
#include <cuda_runtime.h>
#include <cuda_bf16.h>
#include <math.h>
#include <stdint.h>

// Problem constants (fixed shapes)
#define BB   4
#define LL   2048
#define DD   256
#define DIN  512
#define NSS  16
#define DTR_ 16
#define DFF_ 1024
#define TOK  (BB*LL)      // 8192
#define NCH  (BB*DIN)     // 2048 scan channels
#define GCH  16           // scan chunks
#define CL   (LL/GCH)     // 128 steps per chunk

// ---------------- scratch (static device memory) ----------------
__device__ float          g_xz    [TOK * 2 * DIN];
__device__ float          g_xcT   [TOK * DIN];
__device__ float          g_zsT   [TOK * DIN];
__device__ __nv_bfloat16  g_xconvb[TOK * DIN];
__device__ float          g_xdbl  [TOK * 64];
__device__ float          g_dtT   [TOK * DIN];
__device__ float          g_P     [NCH * GCH * NSS];
__device__ float          g_He    [NCH * GCH * NSS];
__device__ float          g_Hin   [NCH * GCH * NSS];
__device__ __nv_bfloat16  g_ygb   [TOK * DIN];
__device__ float          g_ssm   [TOK * DD];
__device__ float          g_y1    [TOK * DD];
__device__ __nv_bfloat16  g_y1b   [TOK * DD];
__device__ __nv_bfloat16  g_h1b   [TOK * DFF_];
__device__ float          g_f2    [TOK * DD];
__device__ __nv_bfloat16  g_xb    [TOK * DD];
__device__ __nv_bfloat16  g_w_in  [2 * DIN * DD];
__device__ __nv_bfloat16  g_w_xp  [64 * DIN];
__device__ __nv_bfloat16  g_w_out [DD * DIN];
__device__ __nv_bfloat16  g_w_fc1 [DFF_ * DD];
__device__ __nv_bfloat16  g_w_fc2 [DD * DFF_];
__device__ float          g_zero  [64];

// ---------------- math helpers ----------------
__device__ __forceinline__ float siluf(float v)     { return v / (1.f + __expf(-v)); }
__device__ __forceinline__ float geluf(float v)     { return 0.5f * v * (1.f + erff(v * 0.70710678118654752f)); }
__device__ __forceinline__ float softplusf(float v) { return fmaxf(v, 0.f) + log1pf(__expf(-fabsf(v))); }

__device__ __forceinline__ uint32_t smem_u32(const void* p) {
    uint32_t a;
    asm("{ .reg .u64 t; cvta.to.shared.u64 t, %1; cvt.u32.u64 %0, t; }" : "=r"(a) : "l"(p));
    return a;
}
__device__ __forceinline__ void ldsm4(uint32_t& r0, uint32_t& r1, uint32_t& r2, uint32_t& r3, uint32_t addr) {
    asm volatile("ldmatrix.sync.aligned.m8n8.x4.shared.b16 {%0,%1,%2,%3}, [%4];"
                 : "=r"(r0), "=r"(r1), "=r"(r2), "=r"(r3) : "r"(addr));
}
__device__ __forceinline__ void mma16816(float* c, const uint32_t* a, const uint32_t* b) {
    asm volatile("mma.sync.aligned.m16n8k16.row.col.f32.bf16.bf16.f32 "
                 "{%0,%1,%2,%3},{%4,%5,%6,%7},{%8,%9},{%0,%1,%2,%3};"
                 : "+f"(c[0]), "+f"(c[1]), "+f"(c[2]), "+f"(c[3])
                 : "r"(a[0]), "r"(a[1]), "r"(a[2]), "r"(a[3]), "r"(b[0]), "r"(b[1]));
}
__device__ __forceinline__ void cp16(uint32_t dst, const void* src) {
    asm volatile("cp.async.cg.shared.global [%0], [%1], 16;" :: "r"(dst), "l"(src));
}
#define CP_COMMIT() asm volatile("cp.async.commit_group;" ::: "memory")

// =======================================================================
// SM80-style bf16 GEMM. BK=64, 3-stage cp.async pipeline,
// ONE __syncthreads per mainloop iteration:
//   wait(kt) -> sync -> prefetch(kt+2) -> compute(kt)
// (prefetch(kt+2) overwrites the stage consumed at kt-1; the top sync
//  is the barrier between that read and this write.)
// BM=128, BN template (128/64), 256 threads = 2(M) x 4(N) warps.
// EPI: 0 none, 1 gelu.  OUTT: 0 fp32, 1 bf16.
// =======================================================================
template<int BN, int EPI, int OUTT>
__global__ __launch_bounds__(256)
void mma_gemm(const __nv_bfloat16* __restrict__ A, const __nv_bfloat16* __restrict__ W,
              const float* __restrict__ bias, void* __restrict__ C, int N, int K)
{
    constexpr int BM  = 128;
    constexpr int BK  = 64;
    constexpr int AST = 72;             // 64 + 8 pad (144B row stride, conflict-free ldsm)
    constexpr int NT  = BN / 32;
    constexpr int ASZ = BM * AST;
    constexpr int BSZ = BN * AST;

    extern __shared__ __nv_bfloat16 smem[];
    __nv_bfloat16* sA = smem;                 // 3 stages
    __nv_bfloat16* sB = smem + 3 * ASZ;       // 3 stages

    const int tid  = threadIdx.x;
    const int wid  = tid >> 5;
    const int lane = tid & 31;
    const int warp_m = wid & 1;
    const int warp_n = wid >> 1;
    const int rowBase = blockIdx.y * BM;
    const int colBase = blockIdx.x * BN;
    const int NK = K >> 6;              // BK=64 chunks (all call sites: NK >= 4)

    auto prefetch = [&](int s, int kc) {
        __nv_bfloat16* As = sA + s * ASZ;
        __nv_bfloat16* Bs = sB + s * BSZ;
        #pragma unroll
        for (int i = 0; i < 4; i++) {           // 128 rows x 8 chunks of 16B
            const int cidx = i * 256 + tid;
            const int row = cidx >> 3, c8 = cidx & 7;
            cp16(smem_u32(&As[row * AST + c8 * 8]),
                 A + (size_t)(rowBase + row) * K + kc * BK + c8 * 8);
        }
        #pragma unroll
        for (int i = 0; i < BN / 32; i++) {     // BN rows x 8 chunks of 16B
            const int cidx = i * 256 + tid;
            const int row = cidx >> 3, c8 = cidx & 7;
            cp16(smem_u32(&Bs[row * AST + c8 * 8]),
                 W + (size_t)(colBase + row) * K + kc * BK + c8 * 8);
        }
    };

    float acc[4][NT][4];
    #pragma unroll
    for (int mi = 0; mi < 4; mi++)
        #pragma unroll
        for (int ni = 0; ni < NT; ni++)
            #pragma unroll
            for (int r = 0; r < 4; r++) acc[mi][ni][r] = 0.f;

    prefetch(0, 0); CP_COMMIT();
    prefetch(1, 1); CP_COMMIT();

    for (int kt = 0; kt < NK; kt++) {
        if (kt + 2 < NK)      asm volatile("cp.async.wait_group 1;" ::: "memory");
        else if (kt + 1 < NK) asm volatile("cp.async.wait_group 1;" ::: "memory");
        else                  asm volatile("cp.async.wait_group 0;" ::: "memory");
        __syncthreads();
        if (kt + 2 < NK) { prefetch((kt + 2) % 3, kt + 2); CP_COMMIT(); }

        const int s = kt % 3;
        __nv_bfloat16* As = sA + s * ASZ;
        __nv_bfloat16* Bs = sB + s * BSZ;
        #pragma unroll
        for (int k = 0; k < 4; k++) {           // four k16 steps per BK=64
            uint32_t af[4][4];
            #pragma unroll
            for (int mi = 0; mi < 4; mi++) {
                const int row = warp_m * 64 + mi * 16 + (lane & 15);
                const int col = k * 16 + (lane >> 4) * 8;
                ldsm4(af[mi][0], af[mi][1], af[mi][2], af[mi][3],
                      smem_u32(&As[row * AST + col]));
            }
            uint32_t bf[NT][2];
            #pragma unroll
            for (int np = 0; np < NT / 2; np++) {
                const int n0 = warp_n * (NT * 8) + np * 16;
                const int q  = lane >> 3;
                const int row = n0 + (q & 1) * 8 + (lane & 7);
                const int col = k * 16 + (q >> 1) * 8;
                uint32_t r0, r1, r2, r3;
                ldsm4(r0, r1, r2, r3, smem_u32(&Bs[row * AST + col]));
                bf[np*2][0] = r0; bf[np*2+1][0] = r1;
                bf[np*2][1] = r2; bf[np*2+1][1] = r3;
            }
            #pragma unroll
            for (int mi = 0; mi < 4; mi++)
                #pragma unroll
                for (int ni = 0; ni < NT; ni++)
                    mma16816(acc[mi][ni], af[mi], bf[ni]);
        }
    }
    __syncthreads();

    const int g  = lane >> 2;
    const int c2 = (lane & 3) * 2;
    #pragma unroll
    for (int mi = 0; mi < 4; mi++) {
        const int row0 = rowBase + warp_m * 64 + mi * 16 + g;
        #pragma unroll
        for (int ni = 0; ni < NT; ni++) {
            const int col = colBase + warp_n * (NT * 8) + ni * 8 + c2;
            const float b0 = bias[col], b1 = bias[col + 1];
            float v00 = acc[mi][ni][0] + b0, v01 = acc[mi][ni][1] + b1;
            float v10 = acc[mi][ni][2] + b0, v11 = acc[mi][ni][3] + b1;
            if (EPI == 1) { v00 = geluf(v00); v01 = geluf(v01); v10 = geluf(v10); v11 = geluf(v11); }
            if (OUTT == 0) {
                *(float2*)((float*)C + (size_t)row0 * N + col)       = make_float2(v00, v01);
                *(float2*)((float*)C + (size_t)(row0 + 8) * N + col) = make_float2(v10, v11);
            } else {
                __nv_bfloat16* Cb = (__nv_bfloat16*)C;
                *(__nv_bfloat162*)(Cb + (size_t)row0 * N + col)       = __float22bfloat162_rn(make_float2(v00, v01));
                *(__nv_bfloat162*)(Cb + (size_t)(row0 + 8) * N + col) = __float22bfloat162_rn(make_float2(v10, v11));
            }
        }
    }
}

// ---------------- converters ----------------
__global__ void cvt_bf16_kernel(const float* __restrict__ in, __nv_bfloat16* __restrict__ out, int n)
{
    int i = blockIdx.x * blockDim.x + threadIdx.x;
    if (i < n) out[i] = __float2bfloat16(in[i]);
}
__global__ void cvt_weights_kernel(const float* __restrict__ a, __nv_bfloat16* __restrict__ oa,
                                   const float* __restrict__ b, __nv_bfloat16* __restrict__ ob,
                                   const float* __restrict__ c, __nv_bfloat16* __restrict__ oc,
                                   const float* __restrict__ d, __nv_bfloat16* __restrict__ od)
{
    int i = blockIdx.x * blockDim.x + threadIdx.x;
    if (i < 2*DIN*DD)            { oa[i] = __float2bfloat16(a[i]); return; }
    i -= 2*DIN*DD;
    if (i < DD*DIN)              { ob[i] = __float2bfloat16(b[i]); return; }
    i -= DD*DIN;
    if (i < DFF_*DD)             { oc[i] = __float2bfloat16(c[i]); return; }
    i -= DFF_*DD;
    if (i < DD*DFF_)             { od[i] = __float2bfloat16(d[i]); }
}
__global__ void pad_xprojw_kernel(const float* __restrict__ W, __nv_bfloat16* __restrict__ out)
{
    int i = blockIdx.x * blockDim.x + threadIdx.x;
    int r = i >> 9, k = i & 511;
    out[i] = __float2bfloat16(r < 48 ? W[r * 512 + k] : 0.f);
}

// ---------------- SIMT SGEMM for dt_proj (K=16) -> dtT channel-major ----------------
__global__ __launch_bounds__(256)
void gemm_kernel_sp(const float* __restrict__ A, int lda,
                    const float* __restrict__ W, const float* __restrict__ bias,
                    float* __restrict__ dtT, int N, int K)
{
    __shared__ float As[16][132];
    __shared__ float Bs[16][132];
    const int tid = threadIdx.x;
    const int tx = tid & 15, ty = tid >> 4;
    const int rowBase = blockIdx.y * 128, colBase = blockIdx.x * 128;
    const int r = tid >> 2, c4 = tid & 3;
    float acc[8][8];
    #pragma unroll
    for (int i = 0; i < 8; i++) {
        #pragma unroll
        for (int j = 0; j < 8; j++) acc[i][j] = 0.f;
    }
    for (int kt = 0; kt < K; kt += 16) {
        #pragma unroll
        for (int rr = r; rr < 128; rr += 64) {
            float4 va = *reinterpret_cast<const float4*>(&A[(size_t)(rowBase + rr) * lda + kt + c4 * 4]);
            As[c4*4+0][rr] = va.x; As[c4*4+1][rr] = va.y; As[c4*4+2][rr] = va.z; As[c4*4+3][rr] = va.w;
            float4 vb = *reinterpret_cast<const float4*>(&W[(size_t)(colBase + rr) * K + kt + c4 * 4]);
            Bs[c4*4+0][rr] = vb.x; Bs[c4*4+1][rr] = vb.y; Bs[c4*4+2][rr] = vb.z; Bs[c4*4+3][rr] = vb.w;
        }
        __syncthreads();
        #pragma unroll
        for (int k = 0; k < 16; k++) {
            float a8[8], b8[8];
            #pragma unroll
            for (int i = 0; i < 8; i++) a8[i] = As[k][ty * 8 + i];
            #pragma unroll
            for (int j = 0; j < 8; j++) b8[j] = Bs[k][tx * 8 + j];
            #pragma unroll
            for (int i = 0; i < 8; i++)
                #pragma unroll
                for (int j = 0; j < 8; j++) acc[i][j] = fmaf(a8[i], b8[j], acc[i][j]);
        }
        __syncthreads();
    }
    const int t0 = rowBase + ty * 8;
    const int b  = t0 >> 11;
    const int l  = t0 & 2047;
    #pragma unroll
    for (int j = 0; j < 8; j++) {
        const int col = colBase + tx * 8 + j;
        const float bj = bias[col];
        float v[8];
        #pragma unroll
        for (int i = 0; i < 8; i++) v[i] = softplusf(acc[i][j] + bj);
        float* o = dtT + ((size_t)(b * DIN + col)) * LL + l;
        *(float4*)(o)     = make_float4(v[0], v[1], v[2], v[3]);
        *(float4*)(o + 4) = make_float4(v[4], v[5], v[6], v[7]);
    }
}

// ---------------- conv+silu with transpose ----------------
__global__ __launch_bounds__(256)
void conv_silu_tr(const float* __restrict__ xz, const float* __restrict__ cw,
                  const float* __restrict__ cb, __nv_bfloat16* __restrict__ xconvb,
                  float* __restrict__ xcT, float* __restrict__ zsT)
{
    __shared__ float sxi[35][33];
    __shared__ float sout[32][33];
    __shared__ float sz[32][33];
    const int l0 = blockIdx.x * 32;
    const int d0 = blockIdx.y * 32;
    const int b  = blockIdx.z;
    const int tid = threadIdx.x;

    for (int i = tid; i < 35 * 32; i += 256) {
        const int r = i >> 5, c = i & 31;
        const int l = l0 - 3 + r;
        sxi[r][c] = (l >= 0) ? xz[((size_t)(b * LL + l)) * (2 * DIN) + d0 + c] : 0.f;
    }
    for (int i = tid; i < 32 * 32; i += 256) {
        const int r = i >> 5, c = i & 31;
        sz[r][c] = xz[((size_t)(b * LL + l0 + r)) * (2 * DIN) + DIN + d0 + c];
    }
    __syncthreads();
    for (int i = tid; i < 32 * 32; i += 256) {
        const int l = i >> 5, c = i & 31;
        const int d = d0 + c;
        float v = cb[d] + cw[d*4+3] * sxi[l+3][c] + cw[d*4+2] * sxi[l+2][c]
                        + cw[d*4+1] * sxi[l+1][c] + cw[d*4+0] * sxi[l][c];
        v = siluf(v);
        sout[l][c] = v;
        xconvb[((size_t)(b * LL + l0 + l)) * DIN + d] = __float2bfloat16(v);
    }
    __syncthreads();
    for (int i = tid; i < 32 * 32; i += 256) {
        const int c = i >> 5, l = i & 31;
        const size_t o = ((size_t)(b * DIN + d0 + c)) * LL + l0 + l;
        xcT[o] = sout[l][c];
        zsT[o] = siluf(sz[l][c]);
    }
}

// ---------------- chunked parallel scan ----------------
__global__ __launch_bounds__(256)
void scan_p1(const float* __restrict__ dtT, const float* __restrict__ xdbl,
             const float* __restrict__ xcT, const float* __restrict__ A_log,
             float* __restrict__ Pst, float* __restrict__ He)
{
    __shared__ __align__(16) float bufB[2][64][16];
    const int tid = threadIdx.x;
    const int cl  = tid >> 4;
    const int n   = tid & 15;
    const int ch  = blockIdx.x * 16 + cl;
    const int b   = ch >> 9, d = ch & (DIN - 1);
    const int chunk = blockIdx.y;
    const int l0  = chunk * CL;

    const float Aval = -expf(A_log[d * NSS + n]);
    const float* dtp = dtT + (size_t)ch * LL + l0;
    const float* xcp = xcT + (size_t)ch * LL + l0;
    const float* xrow = xdbl + ((size_t)(b * LL + l0)) * 64;

    auto fill = [&](int tile, int s) {
        const int r = tid >> 2, c = tid & 3;
        cp16(smem_u32(&bufB[s][r][c * 4]), xrow + ((size_t)(tile * 64 + r)) * 64 + 16 + c * 4);
    };
    fill(0, 0); CP_COMMIT();
    fill(1, 1); CP_COMMIT();

    float h = 0.f, Pp = 1.f;
    #pragma unroll
    for (int tile = 0; tile < CL / 64; tile++) {
        if (tile == 0) asm volatile("cp.async.wait_group 1;" ::: "memory");
        else           asm volatile("cp.async.wait_group 0;" ::: "memory");
        __syncthreads();
        const int s = tile & 1;
        #pragma unroll 8
        for (int j = 0; j < 64; j++) {
            const int l = tile * 64 + j;
            const float dtv = dtp[l];
            const float xv  = xcp[l];
            const float Bv  = bufB[s][j][n];
            const float dA  = __expf(dtv * Aval);
            h = fmaf(dA, h, dtv * Bv * xv);
            Pp *= dA;
        }
        __syncthreads();
    }
    const int idx = (ch * GCH + chunk) * NSS + n;
    Pst[idx] = Pp;
    He[idx]  = h;
}

__global__ __launch_bounds__(256)
void scan_p2(const float* __restrict__ Pst, const float* __restrict__ He,
             float* __restrict__ Hin)
{
    const int t  = blockIdx.x * blockDim.x + threadIdx.x;
    const int ch = t >> 4, n = t & 15;
    float hin = 0.f;
    #pragma unroll
    for (int c = 0; c < GCH; c++) {
        const int idx = (ch * GCH + c) * NSS + n;
        Hin[idx] = hin;
        hin = fmaf(Pst[idx], hin, He[idx]);
    }
}

__global__ __launch_bounds__(256)
void scan_p3(const float* __restrict__ dtT, const float* __restrict__ xdbl,
             const float* __restrict__ xcT, const float* __restrict__ zsT,
             const float* __restrict__ A_log, const float* __restrict__ D_ssm,
             const float* __restrict__ Hin, __nv_bfloat16* __restrict__ yg)
{
    __shared__ __align__(16) float buf[2][64][32];
    const int tid  = threadIdx.x;
    const int lane = tid & 31;
    const int n    = lane & 15;
    const int hw   = lane >> 4;
    const int w    = tid >> 5;
    const int ch   = blockIdx.x * 16 + w * 2 + hw;
    const int b    = ch >> 9, d = ch & (DIN - 1);
    const int chunk = blockIdx.y;
    const int l0   = chunk * CL;

    const float Aval = -expf(A_log[d * NSS + n]);
    const float Dv   = D_ssm[d];
    const float* dtp = dtT + (size_t)ch * LL + l0;
    const float* xcp = xcT + (size_t)ch * LL + l0;
    const float* zp  = zsT + (size_t)ch * LL + l0;
    const float* xrow = xdbl + ((size_t)(b * LL + l0)) * 64;

    auto fill = [&](int tile, int s) {
        #pragma unroll
        for (int i = 0; i < 2; i++) {
            const int idx = i * 256 + tid;
            const int r = idx >> 3, c = idx & 7;
            cp16(smem_u32(&buf[s][r][c * 4]), xrow + ((size_t)(tile * 64 + r)) * 64 + 16 + c * 4);
        }
    };
    fill(0, 0); CP_COMMIT();
    fill(1, 1); CP_COMMIT();

    float h = Hin[(ch * GCH + chunk) * NSS + n];
    #pragma unroll
    for (int tile = 0; tile < CL / 64; tile++) {
        if (tile == 0) asm volatile("cp.async.wait_group 1;" ::: "memory");
        else           asm volatile("cp.async.wait_group 0;" ::: "memory");
        __syncthreads();
        const int s = tile & 1;
        #pragma unroll 4
        for (int j = 0; j < 64; j++) {
            const int l = tile * 64 + j;
            const float dtv = dtp[l];
            const float xv  = xcp[l];
            const float Bv  = buf[s][j][n];
            const float Cv  = buf[s][j][16 + n];
            const float dA  = __expf(dtv * Aval);
            h = fmaf(dA, h, dtv * Bv * xv);
            float p = h * Cv;
            p += __shfl_xor_sync(0xffffffffu, p, 8);
            p += __shfl_xor_sync(0xffffffffu, p, 4);
            p += __shfl_xor_sync(0xffffffffu, p, 2);
            p += __shfl_xor_sync(0xffffffffu, p, 1);
            if (n == 0) {
                const float y = p + xv * Dv;
                yg[((size_t)(b * LL + l0 + l)) * DIN + d] = __float2bfloat16(y * zp[l]);
            }
        }
        __syncthreads();
    }
}

// ---------------- fused residual-add + LayerNorm ----------------
__global__ __launch_bounds__(256)
void ln_add_kernel(const float* __restrict__ a, const float* __restrict__ badd,
                   const float* __restrict__ g, const float* __restrict__ beta,
                   float* __restrict__ out, __nv_bfloat16* __restrict__ outb)
{
    const int row = blockIdx.x;
    const int tid = threadIdx.x;
    const float v = a[(size_t)row * DD + tid] + badd[(size_t)row * DD + tid];
    float s = v, s2 = v * v;
    #pragma unroll
    for (int m = 16; m > 0; m >>= 1) {
        s  += __shfl_xor_sync(0xffffffffu, s,  m);
        s2 += __shfl_xor_sync(0xffffffffu, s2, m);
    }
    __shared__ float sh[8], sh2[8];
    if ((tid & 31) == 0) { sh[tid >> 5] = s; sh2[tid >> 5] = s2; }
    __syncthreads();
    float ts = 0.f, ts2 = 0.f;
    #pragma unroll
    for (int i = 0; i < 8; i++) { ts += sh[i]; ts2 += sh2[i]; }
    const float mean = ts * (1.f / DD);
    const float var  = ts2 * (1.f / DD) - mean * mean;
    const float inv  = rsqrtf(var + 1e-5f);
    const float o = (v - mean) * inv * g[tid] + beta[tid];
    out[(size_t)row * DD + tid] = o;
    if (outb) outb[(size_t)row * DD + tid] = __float2bfloat16(o);
}

// ---------------- launch ----------------
extern "C" void kernel_launch(void* const* d_in, const int* in_sizes, int n_in,
                              void* d_out, int out_size)
{
    const float* x          = (const float*)d_in[0];
    const float* in_proj_w  = (const float*)d_in[1];
    const float* in_proj_b  = (const float*)d_in[2];
    const float* conv_w     = (const float*)d_in[3];
    const float* conv_b     = (const float*)d_in[4];
    const float* x_proj_w   = (const float*)d_in[5];
    const float* dt_proj_w  = (const float*)d_in[6];
    const float* dt_proj_b  = (const float*)d_in[7];
    const float* A_log      = (const float*)d_in[8];
    const float* D_ssm      = (const float*)d_in[9];
    const float* out_proj_w = (const float*)d_in[10];
    const float* out_proj_b = (const float*)d_in[11];
    const float* ln1_g      = (const float*)d_in[12];
    const float* ln1_b      = (const float*)d_in[13];
    const float* fc1_w      = (const float*)d_in[14];
    const float* fc1_b      = (const float*)d_in[15];
    const float* fc2_w      = (const float*)d_in[16];
    const float* fc2_b      = (const float*)d_in[17];
    const float* ln2_g      = (const float*)d_in[18];
    const float* ln2_b      = (const float*)d_in[19];
    float* out = (float*)d_out;

    float *xz, *xcT, *zsT, *xdbl, *dtT, *Pst, *He, *Hin, *ssm, *y1, *f2, *zero;
    __nv_bfloat16 *xconvb, *ygb, *y1b, *h1b, *xb, *w_in, *w_xp, *w_out, *w_fc1, *w_fc2;
    cudaGetSymbolAddress((void**)&xz,     g_xz);
    cudaGetSymbolAddress((void**)&xcT,    g_xcT);
    cudaGetSymbolAddress((void**)&zsT,    g_zsT);
    cudaGetSymbolAddress((void**)&xconvb, g_xconvb);
    cudaGetSymbolAddress((void**)&xdbl,   g_xdbl);
    cudaGetSymbolAddress((void**)&dtT,    g_dtT);
    cudaGetSymbolAddress((void**)&Pst,    g_P);
    cudaGetSymbolAddress((void**)&He,     g_He);
    cudaGetSymbolAddress((void**)&Hin,    g_Hin);
    cudaGetSymbolAddress((void**)&ygb,    g_ygb);
    cudaGetSymbolAddress((void**)&ssm,    g_ssm);
    cudaGetSymbolAddress((void**)&y1,     g_y1);
    cudaGetSymbolAddress((void**)&y1b,    g_y1b);
    cudaGetSymbolAddress((void**)&h1b,    g_h1b);
    cudaGetSymbolAddress((void**)&f2,     g_f2);
    cudaGetSymbolAddress((void**)&xb,     g_xb);
    cudaGetSymbolAddress((void**)&w_in,   g_w_in);
    cudaGetSymbolAddress((void**)&w_xp,   g_w_xp);
    cudaGetSymbolAddress((void**)&w_out,  g_w_out);
    cudaGetSymbolAddress((void**)&w_fc1,  g_w_fc1);
    cudaGetSymbolAddress((void**)&w_fc2,  g_w_fc2);
    cudaGetSymbolAddress((void**)&zero,   g_zero);

    // dynamic smem: 3 stages of (BM + BN) * 72 bf16
    const int SM128 = 3 * (128 + 128) * 72 * 2;  // 110592
    const int SM64  = 3 * (128 + 64)  * 72 * 2;  // 82944
    cudaFuncSetAttribute(mma_gemm<128,0,0>, cudaFuncAttributeMaxDynamicSharedMemorySize, SM128);
    cudaFuncSetAttribute(mma_gemm<128,1,1>, cudaFuncAttributeMaxDynamicSharedMemorySize, SM128);
    cudaFuncSetAttribute(mma_gemm<128,1,0>, cudaFuncAttributeMaxDynamicSharedMemorySize, SM128);
    cudaFuncSetAttribute(mma_gemm<64,0,0>,  cudaFuncAttributeMaxDynamicSharedMemorySize, SM64);

    // 1-3) conversions (in_proj GEMM stays in launch slot 4 for profiling)
    cvt_bf16_kernel<<<(TOK*DD+255)/256, 256>>>(x, xb, TOK*DD);
    cvt_weights_kernel<<<((2*DIN*DD + DD*DIN + DFF_*DD + DD*DFF_) + 255)/256, 256>>>(
        in_proj_w, w_in, out_proj_w, w_out, fc1_w, w_fc1, fc2_w, w_fc2);
    pad_xprojw_kernel<<<(64*DIN+255)/256, 256>>>(x_proj_w, w_xp);
    // 4) in_proj GEMM -> xz fp32   [PROFILED]
    mma_gemm<128,0,0><<<dim3(2*DIN/128, TOK/128), 256, SM128>>>(xb, w_in, in_proj_b, xz, 2*DIN, DD);
    // 5) conv + silu + transpose
    conv_silu_tr<<<dim3(LL/32, DIN/32, BB), 256>>>(xz, conv_w, conv_b, xconvb, xcT, zsT);
    // 6) x_proj GEMM -> xdbl
    mma_gemm<64,0,0><<<dim3(1, TOK/128), 256, SM64>>>(xconvb, w_xp, zero, xdbl, 64, DIN);
    // 7) dt_proj + softplus -> dtT channel-major
    gemm_kernel_sp<<<dim3(DIN/128, TOK/128), 256>>>(xdbl, 64, dt_proj_w, dt_proj_b, dtT, DIN, DTR_);
    // 8-10) chunked parallel scan
    scan_p1<<<dim3(NCH/16, GCH), 256>>>(dtT, xdbl, xcT, A_log, Pst, He);
    scan_p2<<<(NCH*NSS)/256, 256>>>(Pst, He, Hin);
    scan_p3<<<dim3(NCH/16, GCH), 256>>>(dtT, xdbl, xcT, zsT, A_log, D_ssm, Hin, ygb);
    // 11) out_proj GEMM -> ssm
    mma_gemm<128,0,0><<<dim3(DD/128, TOK/128), 256, SM128>>>(ygb, w_out, out_proj_b, ssm, DD, DIN);
    // 12) LN1(x + ssm)
    ln_add_kernel<<<TOK, 256>>>(x, ssm, ln1_g, ln1_b, y1, y1b);
    // 13) fc1 + gelu
    mma_gemm<128,1,1><<<dim3(DFF_/128, TOK/128), 256, SM128>>>(y1b, w_fc1, fc1_b, h1b, DFF_, DD);
    // 14) fc2 + gelu
    mma_gemm<128,1,0><<<dim3(DD/128, TOK/128), 256, SM128>>>(h1b, w_fc2, fc2_b, f2, DD, DFF_);
    // 15) LN2(y1 + ffn) -> out
    ln_add_kernel<<<TOK, 256>>>(y1, f2, ln2_g, ln2_b, out, (__nv_bfloat16*)0);
}